// round 7
// baseline (speedup 1.0000x reference)
#include <cuda_runtime.h>
#include <cuda_fp16.h>
#include <math.h>
#include <stdint.h>

#define BATCH 4
#define LSEQ  2048
#define DMOD  1024
#define DST   16
#define KCONV 4
#define DINN  2048
#define MROWS (BATCH*LSEQ)   /* 8192 */

// ---------------- scratch (device globals) -----------------------------------
__device__ __align__(128) __half g_xib[(size_t)MROWS * DINN];
__device__ __align__(128) __half g_xsb[(size_t)MROWS * DINN];
__device__ __align__(128) float g_bc[(size_t)MROWS * 32];
__device__ __align__(128) float g_hs[(size_t)MROWS * DST];
__device__ __align__(128) float g_At[16*16*16];
__device__ __align__(128) float g_Wred[DMOD*DST];
__device__ __align__(128) float g_bconst[DMOD];
__device__ __align__(128) float g_zero[DMOD];
__device__ __align__(128) __half g_xh[(size_t)MROWS*DMOD], g_xl[(size_t)MROWS*DMOD];
__device__ __align__(128) __half g_winh[(size_t)DINN*DMOD];
__device__ __align__(128) __half g_winTh[(size_t)DMOD*DINN], g_winTl[(size_t)DMOD*DINN];
__device__ __align__(128) __half g_woh[(size_t)DMOD*DINN], g_wol[(size_t)DMOD*DINN];
__device__ __align__(128) __half g_wcombh[(size_t)DMOD*DMOD];
__device__ __align__(128) __half g_wxh[(size_t)128*DINN];

// ============================ PTX helpers (arch-agnostic) ====================
__device__ __forceinline__ uint32_t smem_u32(const void* p) {
    uint32_t a;
    asm("{ .reg .u64 t; cvta.to.shared.u64 t, %1; cvt.u32.u64 %0, t; }"
        : "=r"(a) : "l"(p));
    return a;
}
__device__ __forceinline__ void cp16(uint32_t s, const void* g) {
    asm volatile("cp.async.cg.shared.global [%0], [%1], 16;" :: "r"(s), "l"(g));
}
#define CP_COMMIT() asm volatile("cp.async.commit_group;" ::: "memory")
template<int N> __device__ __forceinline__ void cp_wait() {
    asm volatile("cp.async.wait_group %0;" :: "n"(N) : "memory");
}
__device__ __forceinline__ void ldsm_x4(uint32_t& r0, uint32_t& r1,
                                        uint32_t& r2, uint32_t& r3, uint32_t a) {
    asm volatile("ldmatrix.sync.aligned.m8n8.x4.shared.b16 {%0,%1,%2,%3}, [%4];"
                 : "=r"(r0), "=r"(r1), "=r"(r2), "=r"(r3) : "r"(a));
}
__device__ __forceinline__ void mma16816(float* c,
    uint32_t a0, uint32_t a1, uint32_t a2, uint32_t a3, uint32_t b0, uint32_t b1) {
    asm volatile(
        "mma.sync.aligned.m16n8k16.row.col.f32.f16.f16.f32 "
        "{%0,%1,%2,%3}, {%4,%5,%6,%7}, {%8,%9}, {%0,%1,%2,%3};"
        : "+f"(c[0]), "+f"(c[1]), "+f"(c[2]), "+f"(c[3])
        : "r"(a0), "r"(a1), "r"(a2), "r"(a3), "r"(b0), "r"(b1));
}
__device__ __forceinline__ float tanh_fast(float x) {
    float r;
    asm("tanh.approx.f32 %0, %1;" : "=f"(r) : "f"(x));
    return r;
}
__device__ __forceinline__ uint32_t swz(uint32_t bo) { return bo ^ ((bo >> 3) & 0x70); }

// ================== split-fp16 GEMM via mma.sync: C = A @ B^T ================
// MODE 1: fp32 + bias      MODE 2: fp16 + bias      MODE 3: fp32 + bias, n<32
// PASSES: 1 = Ah*Bh
//         2 = Ah*Bh + Al*Bh   (A split, B hi-only)
//         3 = Ah*Bh + Ah*Bl + Al*Bh  (both split)
template<int ROWS>
__device__ __forceinline__ void load_tile_async(const __half* __restrict__ g,
                                                long row0, int ld, int k0,
                                                uint32_t sb, int tid) {
    #pragma unroll
    for (int t = 0; t < ROWS/32; t++) {
        int idx = tid + t * 256;
        int r = idx >> 3, cv = idx & 7;
        cp16(sb + swz((uint32_t)(r * 128 + cv * 16)),
             g + (row0 + r) * (long)ld + k0 + cv * 8);
    }
}

template<int MODE, int PASSES, int BN_>
__global__ __launch_bounds__(256, 1)
void gemm_mma(const __half* __restrict__ Ah, const __half* __restrict__ Al, int lda,
              const __half* __restrict__ Bh, const __half* __restrict__ Bl, int ldb,
              const float* __restrict__ bias,
              float* __restrict__ Cout, int ldc,
              __half* __restrict__ outh, int ldr,
              int K)
{
    constexpr int ATILE = 16384;
    constexpr int BTILE = BN_ * 128;
    constexpr int OFF_AL = ATILE;
    constexpr int OFF_BH = (PASSES >= 2) ? 2*ATILE : ATILE;
    constexpr int OFF_BL = OFF_BH + BTILE;
    constexpr int STAGE  = OFF_BH + ((PASSES == 3) ? 2*BTILE : BTILE);
    constexpr int NF = BN_ / 16;
    constexpr int NB = BN_ / 32;

    extern __shared__ char smem_raw[];
    uint32_t raw = smem_u32(smem_raw);
    const uint32_t sbase = (raw + 1023u) & ~1023u;

    const int tid  = threadIdx.x;
    const int wid  = tid >> 5, lane = tid & 31;
    const int warpM = wid & 3, warpN = wid >> 2;
    const long m0 = (long)blockIdx.y * 128;
    const int  n0 = blockIdx.x * BN_;

    float acc[2][NF][4];
    #pragma unroll
    for (int i = 0; i < 2; i++)
        #pragma unroll
        for (int j = 0; j < NF; j++)
            #pragma unroll
            for (int q = 0; q < 4; q++) acc[i][j][q] = 0.f;

    const int rowA0 = warpM * 32 + (lane & 7) + ((lane >> 3) & 1) * 8;
    const int khA   = (lane >> 4) & 1;
    const int rowB0 = warpN * (BN_/2) + (lane & 7) + ((lane >> 4) & 1) * 8;
    const int khB   = (lane >> 3) & 1;

    const int NC = K / 64;

    auto issue = [&](int c) {
        uint32_t st = sbase + (uint32_t)(c % 3) * STAGE;
        int k0 = c * 64;
        load_tile_async<128>(Ah, m0, lda, k0, st, tid);
        if (PASSES >= 2) load_tile_async<128>(Al, m0, lda, k0, st + OFF_AL, tid);
        load_tile_async<BN_>(Bh, n0, ldb, k0, st + OFF_BH, tid);
        if (PASSES == 3) load_tile_async<BN_>(Bl, n0, ldb, k0, st + OFF_BL, tid);
        CP_COMMIT();
    };

    issue(0);
    if (NC > 1) issue(1);

    for (int c = 0; c < NC; c++) {
        if (c + 2 < NC)      { issue(c + 2); cp_wait<2>(); }
        else if (c + 1 < NC) { cp_wait<1>(); }
        else                 { cp_wait<0>(); }
        __syncthreads();

        uint32_t st = sbase + (uint32_t)(c % 3) * STAGE;
        #pragma unroll
        for (int ks = 0; ks < 4; ks++) {
            uint32_t ah[2][4], al[2][4], bh[NF][2], bl[NF][2];
            #pragma unroll
            for (int mi = 0; mi < 2; mi++) {
                uint32_t bo = swz((uint32_t)((rowA0 + mi*16) * 128 + ks*32 + khA*16));
                ldsm_x4(ah[mi][0], ah[mi][1], ah[mi][2], ah[mi][3], st + bo);
                if (PASSES >= 2)
                    ldsm_x4(al[mi][0], al[mi][1], al[mi][2], al[mi][3], st + OFF_AL + bo);
            }
            #pragma unroll
            for (int nb = 0; nb < NB; nb++) {
                uint32_t bo = swz((uint32_t)((rowB0 + nb*16) * 128 + ks*32 + khB*16));
                ldsm_x4(bh[nb*2][0], bh[nb*2][1], bh[nb*2+1][0], bh[nb*2+1][1],
                        st + OFF_BH + bo);
                if (PASSES == 3)
                    ldsm_x4(bl[nb*2][0], bl[nb*2][1], bl[nb*2+1][0], bl[nb*2+1][1],
                            st + OFF_BL + bo);
            }
            #pragma unroll
            for (int mi = 0; mi < 2; mi++)
                #pragma unroll
                for (int nf = 0; nf < NF; nf++)
                    mma16816(acc[mi][nf], ah[mi][0], ah[mi][1], ah[mi][2], ah[mi][3],
                             bh[nf][0], bh[nf][1]);
            if (PASSES == 3) {
                #pragma unroll
                for (int mi = 0; mi < 2; mi++)
                    #pragma unroll
                    for (int nf = 0; nf < NF; nf++)
                        mma16816(acc[mi][nf], ah[mi][0], ah[mi][1], ah[mi][2], ah[mi][3],
                                 bl[nf][0], bl[nf][1]);
            }
            if (PASSES >= 2) {
                #pragma unroll
                for (int mi = 0; mi < 2; mi++)
                    #pragma unroll
                    for (int nf = 0; nf < NF; nf++)
                        mma16816(acc[mi][nf], al[mi][0], al[mi][1], al[mi][2], al[mi][3],
                                 bh[nf][0], bh[nf][1]);
            }
        }
        __syncthreads();
    }

    const int g  = lane >> 2, tg = lane & 3;
    #pragma unroll
    for (int mi = 0; mi < 2; mi++) {
        #pragma unroll
        for (int h = 0; h < 2; h++) {
            long m = m0 + warpM * 32 + mi * 16 + h * 8 + g;
            #pragma unroll
            for (int nf = 0; nf < NF; nf++) {
                int n = n0 + warpN * (BN_/2) + nf * 8 + tg * 2;
                if (MODE == 3 && n >= 32) continue;
                float2 bv = *reinterpret_cast<const float2*>(&bias[n]);
                float v0 = acc[mi][nf][h*2+0] + bv.x;
                float v1 = acc[mi][nf][h*2+1] + bv.y;
                if (MODE == 2) {
                    __half2 p;
                    p.x = __float2half_rn(v0);
                    p.y = __float2half_rn(v1);
                    *reinterpret_cast<__half2*>(&outh[m * (long)ldr + n]) = p;
                } else {
                    *reinterpret_cast<float2*>(&Cout[m * (long)ldc + n]) =
                        make_float2(v0, v1);
                }
            }
        }
    }
}

// ---------------- prep kernels -----------------------------------------------
__global__ void prep_at(const float* __restrict__ dt, const float* __restrict__ A,
                        float* __restrict__ At) {
    int t = blockIdx.x * blockDim.x + threadIdx.x;
    if (t < 4096) {
        int j = t >> 8, e = t & 255;
        At[t] = expf(expf(dt[j]) * A[e]);
    }
}

__global__ void prep_wred(const float* __restrict__ Wout, float* __restrict__ Wred) {
    int t = blockIdx.x * blockDim.x + threadIdx.x;
    if (t < DMOD * DST) {
        int m = t >> 4, s = t & 15;
        float sum = 0.f;
        #pragma unroll 8
        for (int r = 0; r < DINN / DST; r++)
            sum += Wout[(size_t)m * DINN + r * DST + s];
        Wred[t] = sum;
    }
}

__global__ void split_f32_v4(const float* __restrict__ src,
                             __half* __restrict__ hi,
                             __half* __restrict__ lo, long n4) {
    long t = (long)blockIdx.x * blockDim.x + threadIdx.x;
    if (t < n4) {
        float4 v = reinterpret_cast<const float4*>(src)[t];
        __half h0 = __float2half_rn(v.x), h1 = __float2half_rn(v.y);
        __half h2 = __float2half_rn(v.z), h3 = __float2half_rn(v.w);
        __half2 ha; ha.x = h0; ha.y = h1;
        __half2 hb; hb.x = h2; hb.y = h3;
        __half2 la, lb;
        la.x = __float2half_rn(v.x - __half2float(h0));
        la.y = __float2half_rn(v.y - __half2float(h1));
        lb.x = __float2half_rn(v.z - __half2float(h2));
        lb.y = __float2half_rn(v.w - __half2float(h3));
        reinterpret_cast<__half2*>(hi)[t*2]   = ha;
        reinterpret_cast<__half2*>(hi)[t*2+1] = hb;
        reinterpret_cast<__half2*>(lo)[t*2]   = la;
        reinterpret_cast<__half2*>(lo)[t*2+1] = lb;
    }
}

__global__ void split_hi_v4(const float* __restrict__ src,
                            __half* __restrict__ hi, long n4) {
    long t = (long)blockIdx.x * blockDim.x + threadIdx.x;
    if (t < n4) {
        float4 v = reinterpret_cast<const float4*>(src)[t];
        __half2 ha; ha.x = __float2half_rn(v.x); ha.y = __float2half_rn(v.y);
        __half2 hb; hb.x = __float2half_rn(v.z); hb.y = __float2half_rn(v.w);
        reinterpret_cast<__half2*>(hi)[t*2]   = ha;
        reinterpret_cast<__half2*>(hi)[t*2+1] = hb;
    }
}

// transpose + split: src [DINN, DMOD] -> th/tl [DMOD, DINN]
__global__ void transpose_split(const float* __restrict__ src,
                                __half* __restrict__ th,
                                __half* __restrict__ tl) {
    __shared__ float tile[32][33];
    int di0 = blockIdx.x * 32, dm0 = blockIdx.y * 32;
    int tx = threadIdx.x, ty = threadIdx.y;
    #pragma unroll
    for (int i = 0; i < 32; i += 8)
        tile[ty + i][tx] = src[(size_t)(di0 + ty + i) * DMOD + dm0 + tx];
    __syncthreads();
    #pragma unroll
    for (int i = 0; i < 32; i += 8) {
        float v = tile[tx][ty + i];
        __half h = __float2half_rn(v);
        size_t o = (size_t)(dm0 + ty + i) * DINN + di0 + tx;
        th[o] = h;
        tl[o] = __float2half_rn(v - __half2float(h));
    }
}

__global__ void prep_bconst(const float* __restrict__ Wout,
                            const float* __restrict__ b2,
                            const float* __restrict__ bout,
                            float* __restrict__ bc) {
    int n = blockIdx.x * 8 + (threadIdx.x >> 5);
    int lane = threadIdx.x & 31;
    float s = 0.f;
    for (int k = lane; k < DINN; k += 32)
        s = fmaf(Wout[(size_t)n * DINN + k], b2[k], s);
    #pragma unroll
    for (int o = 16; o; o >>= 1) s += __shfl_xor_sync(0xffffffffu, s, o);
    if (lane == 0) bc[n] = s + bout[n];
}

__global__ void prep_wx(const float* __restrict__ Wx, __half* __restrict__ o) {
    int t = blockIdx.x * blockDim.x + threadIdx.x;
    if (t < 128 * DINN) {
        int n = t / DINN, k = t % DINN;
        o[t] = __float2half_rn((n < 32) ? Wx[(size_t)n * DINN + k] : 0.f);
    }
}

// ---------------- depthwise causal conv (K=4) + SiLU, fp16 8-wide ------------
__global__ void conv_silu(const __half* __restrict__ xi,
                          const float* __restrict__ w,
                          const float* __restrict__ cb,
                          __half* __restrict__ xs)
{
    long t = (long)blockIdx.x * blockDim.x + threadIdx.x;   // over MROWS*DINN/8
    if (t >= (long)MROWS * (DINN/8)) return;
    int  c8 = (int)(t % (DINN/8)) * 8;
    long bl = t / (DINN/8);
    int  l  = (int)(bl & (LSEQ - 1));
    long row0 = bl - l;

    float acc[8];
    {
        float4 b0 = *reinterpret_cast<const float4*>(&cb[c8]);
        float4 b1 = *reinterpret_cast<const float4*>(&cb[c8 + 4]);
        acc[0]=b0.x; acc[1]=b0.y; acc[2]=b0.z; acc[3]=b0.w;
        acc[4]=b1.x; acc[5]=b1.y; acc[6]=b1.z; acc[7]=b1.w;
    }
    #pragma unroll
    for (int k = 0; k < KCONV; k++) {
        int ll = l - (KCONV - 1) + k;
        if (ll >= 0) {
            uint4 raw = *reinterpret_cast<const uint4*>(
                &xi[(size_t)(row0 + ll) * DINN + c8]);
            const __half2* hp = reinterpret_cast<const __half2*>(&raw);
            #pragma unroll
            for (int j = 0; j < 4; j++) {
                float2 xv = __half22float2(hp[j]);
                acc[2*j+0] = fmaf(xv.x, w[(c8 + 2*j + 0) * 4 + k], acc[2*j+0]);
                acc[2*j+1] = fmaf(xv.y, w[(c8 + 2*j + 1) * 4 + k], acc[2*j+1]);
            }
        }
    }
    uint4 outr;
    __half2* op = reinterpret_cast<__half2*>(&outr);
    #pragma unroll
    for (int j = 0; j < 4; j++) {
        float a0 = acc[2*j+0], a1 = acc[2*j+1];
        a0 = a0 / (1.f + expf(-a0));
        a1 = a1 / (1.f + expf(-a1));
        op[j] = __floats2half2_rn(a0, a1);
    }
    *reinterpret_cast<uint4*>(&xs[(size_t)bl * DINN + c8]) = outr;
}

// ---------------- sequential nonlinear scan ----------------------------------
__global__ void scan_kernel(const float* __restrict__ bc,
                            const float* __restrict__ At,
                            float* __restrict__ hs)
{
    const int b = blockIdx.x;
    const int i = threadIdx.x;
    const unsigned mask = 0xffffu;
    __shared__ float sAt[16*16*16];
    __shared__ float sBC[64*32];

    for (int t = i; t < 4096/4; t += 16)
        reinterpret_cast<float4*>(sAt)[t] = reinterpret_cast<const float4*>(At)[t];

    const float* bcb = bc + (size_t)b*LSEQ*32;
    float*       hsb = hs + (size_t)b*LSEQ*DST;
    float h = 0.f;

    for (int l0 = 0; l0 < LSEQ; l0 += 64) {
        __syncwarp(mask);
        const float4* src = reinterpret_cast<const float4*>(bcb + (size_t)l0*32);
        for (int t = i; t < 64*32/4; t += 16)
            reinterpret_cast<float4*>(sBC)[t] = src[t];
        __syncwarp(mask);
        for (int ll = 0; ll < 64; ll++) {
            int l = l0 + ll;
            float Bv = sBC[ll*32 + i];
            float Cv = sBC[ll*32 + 16 + i];
            const float* Ar = &sAt[((l & 15) << 8) + (i << 4)];
            float a0 = Cv, a1 = 0.f, a2 = 0.f, a3 = Bv * h;
            #pragma unroll
            for (int j = 0; j < 16; j += 4) {
                a0 = fmaf(Ar[j+0], __shfl_sync(mask, h, j+0), a0);
                a1 = fmaf(Ar[j+1], __shfl_sync(mask, h, j+1), a1);
                a2 = fmaf(Ar[j+2], __shfl_sync(mask, h, j+2), a2);
                a3 = fmaf(Ar[j+3], __shfl_sync(mask, h, j+3), a3);
            }
            h = tanh_fast((a0 + a1) + (a2 + a3));
            hsb[(size_t)l*DST + i] = h;
        }
    }
}

// ---------------- rank-16 update: out += hs @ Wred^T (fp32) ------------------
__global__ void rank16_add(float* __restrict__ out,
                           const float* __restrict__ hs,
                           const float* __restrict__ Wred) {
    int m = blockIdx.x;
    int t = threadIdx.x;
    __shared__ float sh[16];
    if (t < 16) sh[t] = hs[(size_t)m * 16 + t];
    __syncthreads();
    float4 v = reinterpret_cast<float4*>(out)[(size_t)m * 256 + t];
    int n0 = t * 4;
    #pragma unroll
    for (int s = 0; s < 16; s++) {
        float hv = sh[s];
        v.x = fmaf(hv, Wred[(n0+0)*16 + s], v.x);
        v.y = fmaf(hv, Wred[(n0+1)*16 + s], v.y);
        v.z = fmaf(hv, Wred[(n0+2)*16 + s], v.z);
        v.w = fmaf(hv, Wred[(n0+3)*16 + s], v.w);
    }
    reinterpret_cast<float4*>(out)[(size_t)m * 256 + t] = v;
}

// ---------------- stream / event singletons ----------------------------------
static cudaStream_t side_stream() {
    static cudaStream_t s = []() {
        cudaStream_t t;
        cudaStreamCreateWithFlags(&t, cudaStreamNonBlocking);
        return t;
    }();
    return s;
}
static cudaEvent_t ev(int i) {
    static cudaEvent_t e[4] = {nullptr, nullptr, nullptr, nullptr};
    if (!e[0])
        for (int k = 0; k < 4; k++)
            cudaEventCreateWithFlags(&e[k], cudaEventDisableTiming);
    return e[i];
}

// ---------------- launcher ----------------------------------------------------
extern "C" void kernel_launch(void* const* d_in, const int* in_sizes, int n_in,
                              void* d_out, int out_size)
{
    const float* x      = (const float*)d_in[0];
    const float* W_in   = (const float*)d_in[1];
    const float* b_in   = (const float*)d_in[2];
    const float* conv_w = (const float*)d_in[3];
    const float* conv_b = (const float*)d_in[4];
    const float* W_x    = (const float*)d_in[5];
    const float* b_x    = (const float*)d_in[6];
    const float* dt     = (const float*)d_in[7];
    const float* A      = (const float*)d_in[8];
    const float* W_out  = (const float*)d_in[10];
    const float* b_out  = (const float*)d_in[11];
    float* out = (float*)d_out;

    float *bcv, *hsp, *Atp, *Wred, *bconst, *zerov;
    __half *xib, *xsb, *xh, *xl, *winh, *winTh, *winTl, *woh, *wol, *wcombh, *wxh;
    cudaGetSymbolAddress((void**)&xib,    g_xib);
    cudaGetSymbolAddress((void**)&xsb,    g_xsb);
    cudaGetSymbolAddress((void**)&bcv,    g_bc);
    cudaGetSymbolAddress((void**)&hsp,    g_hs);
    cudaGetSymbolAddress((void**)&Atp,    g_At);
    cudaGetSymbolAddress((void**)&Wred,   g_Wred);
    cudaGetSymbolAddress((void**)&bconst, g_bconst);
    cudaGetSymbolAddress((void**)&zerov,  g_zero);
    cudaGetSymbolAddress((void**)&xh,     g_xh);
    cudaGetSymbolAddress((void**)&xl,     g_xl);
    cudaGetSymbolAddress((void**)&winh,   g_winh);
    cudaGetSymbolAddress((void**)&winTh,  g_winTh);
    cudaGetSymbolAddress((void**)&winTl,  g_winTl);
    cudaGetSymbolAddress((void**)&woh,    g_woh);
    cudaGetSymbolAddress((void**)&wol,    g_wol);
    cudaGetSymbolAddress((void**)&wcombh, g_wcombh);
    cudaGetSymbolAddress((void**)&wxh,    g_wxh);

    const int SM_XI   = 3 * (2 * 16384) + 1024;               // P1 BN128
    const int SM_BC   = 3 * (16384 + 64*128) + 1024;          // P1 BN64
    const int SM_P364 = 3 * (2 * 16384 + 2 * 64*128) + 1024;  // P3 BN64 (Wcomb)
    const int SM_P2128= 3 * (3 * 16384) + 1024;               // P2 BN128 (out)
    cudaFuncSetAttribute(gemm_mma<2,1,128>, cudaFuncAttributeMaxDynamicSharedMemorySize, SM_XI);
    cudaFuncSetAttribute(gemm_mma<3,1,64>,  cudaFuncAttributeMaxDynamicSharedMemorySize, SM_BC);
    cudaFuncSetAttribute(gemm_mma<2,3,64>,  cudaFuncAttributeMaxDynamicSharedMemorySize, SM_P364);
    cudaFuncSetAttribute(gemm_mma<1,2,128>, cudaFuncAttributeMaxDynamicSharedMemorySize, SM_P2128);

    cudaStream_t sd = side_stream();
    cudaEvent_t e_fork = ev(0), e_x = ev(1), e_hs = ev(2), e_done = ev(3);

    // ---- fork side stream at capture start ----
    cudaEventRecord(e_fork, 0);
    cudaStreamWaitEvent(sd, e_fork, 0);

    // ==== stream 0: xi chain (gemm1a deliberately placed as launch #4) ====
    split_f32_v4<<<(int)(((long)MROWS*DMOD/4 + 255)/256), 256>>>(x, xh, xl, (long)MROWS*DMOD/4);
    cudaEventRecord(e_x, 0);
    split_hi_v4<<<(int)(((long)DINN*DMOD/4 + 255)/256), 256>>>(W_in, winh, (long)DINN*DMOD/4);
    prep_at<<<16, 256>>>(dt, A, Atp);
    gemm_mma<2,1,128><<<dim3(DINN/128, MROWS/128), 256, SM_XI>>>(      // launch #4
        xh, nullptr, DMOD, winh, nullptr, DMOD, b_in,
        nullptr, 0, xib, DINN, DMOD);
    conv_silu<<<(int)(((long)MROWS*(DINN/8) + 255)/256), 256>>>(xib, conv_w, conv_b, xsb);
    prep_wx<<<(128*DINN + 255)/256, 256>>>(W_x, wxh);
    gemm_mma<3,1,64><<<dim3(1, MROWS/128), 256, SM_BC>>>(
        xsb, nullptr, DINN, wxh, nullptr, DINN, b_x,
        bcv, 32, nullptr, 0, DINN);
    scan_kernel<<<BATCH, 16>>>(bcv, Atp, hsp);
    cudaEventRecord(e_hs, 0);

    // ==== side stream: output chain ====
    split_f32_v4<<<(int)(((long)DMOD*DINN/4 + 255)/256), 256, 0, sd>>>(
        W_out, woh, wol, (long)DMOD*DINN/4);
    transpose_split<<<dim3(DINN/32, DMOD/32), dim3(32, 8), 0, sd>>>(
        W_in + (size_t)DINN*DMOD, winTh, winTl);
    prep_wred<<<64, 256, 0, sd>>>(W_out, Wred);
    prep_bconst<<<DMOD/8, 256, 0, sd>>>(W_out, b_in + DINN, b_out, bconst);

    // Wcomb = Wout @ Win2 (1024x1024, K=2048), 3-pass, fp16-hi out
    gemm_mma<2,3,64><<<dim3(DMOD/64, DMOD/128), 256, SM_P364, sd>>>(
        woh, wol, DINN, winTh, winTl, DINN, zerov,
        nullptr, 0, wcombh, DMOD, DINN);
    // out = x @ Wcomb^T + bconst (2-pass: x split, Wcomb hi)
    cudaStreamWaitEvent(sd, e_x, 0);
    gemm_mma<1,2,128><<<dim3(DMOD/128, MROWS/128), 256, SM_P2128, sd>>>(
        xh, xl, DMOD, wcombh, nullptr, DMOD, bconst,
        out, DMOD, nullptr, 0, DMOD);
    // out += hs @ Wred^T
    cudaStreamWaitEvent(sd, e_hs, 0);
    rank16_add<<<MROWS, 256, 0, sd>>>(out, hsp, Wred);
    cudaEventRecord(e_done, sd);

    // ---- join side stream before capture ends ----
    cudaStreamWaitEvent(0, e_done, 0);
}

// round 8
// speedup vs baseline: 1.1087x; 1.1087x over previous
#include <cuda_runtime.h>
#include <cuda_fp16.h>
#include <math.h>
#include <stdint.h>

#define BATCH 4
#define LSEQ  2048
#define DMOD  1024
#define DST   16
#define KCONV 4
#define DINN  2048
#define MROWS (BATCH*LSEQ)   /* 8192 */

// ---------------- scratch (device globals) -----------------------------------
__device__ __align__(128) __half g_xib[(size_t)MROWS * DINN];
__device__ __align__(128) __half g_xsb[(size_t)MROWS * DINN];
__device__ __align__(128) float g_bc[(size_t)MROWS * 32];
__device__ __align__(128) float g_hs[(size_t)MROWS * DST];
__device__ __align__(128) float g_At[16*16*16];
__device__ __align__(128) float g_Wred[DMOD*DST];
__device__ __align__(128) float g_bconst[DMOD];
__device__ __align__(128) float g_zero[DMOD];
__device__ __align__(128) __half g_xh[(size_t)MROWS*DMOD], g_xl[(size_t)MROWS*DMOD];
__device__ __align__(128) __half g_winh[(size_t)DINN*DMOD];
__device__ __align__(128) __half g_winTh[(size_t)DMOD*DINN], g_winTl[(size_t)DMOD*DINN];
__device__ __align__(128) __half g_woh[(size_t)DMOD*DINN], g_wol[(size_t)DMOD*DINN];
__device__ __align__(128) __half g_wcombh[(size_t)DMOD*DMOD];
__device__ __align__(128) __half g_wxh[(size_t)128*DINN];

// ============================ PTX helpers (arch-agnostic) ====================
__device__ __forceinline__ uint32_t smem_u32(const void* p) {
    uint32_t a;
    asm("{ .reg .u64 t; cvta.to.shared.u64 t, %1; cvt.u32.u64 %0, t; }"
        : "=r"(a) : "l"(p));
    return a;
}
__device__ __forceinline__ void cp16(uint32_t s, const void* g) {
    asm volatile("cp.async.cg.shared.global [%0], [%1], 16;" :: "r"(s), "l"(g));
}
#define CP_COMMIT() asm volatile("cp.async.commit_group;" ::: "memory")
template<int N> __device__ __forceinline__ void cp_wait() {
    asm volatile("cp.async.wait_group %0;" :: "n"(N) : "memory");
}
__device__ __forceinline__ void ldsm_x4(uint32_t& r0, uint32_t& r1,
                                        uint32_t& r2, uint32_t& r3, uint32_t a) {
    asm volatile("ldmatrix.sync.aligned.m8n8.x4.shared.b16 {%0,%1,%2,%3}, [%4];"
                 : "=r"(r0), "=r"(r1), "=r"(r2), "=r"(r3) : "r"(a));
}
__device__ __forceinline__ void mma16816(float* c,
    uint32_t a0, uint32_t a1, uint32_t a2, uint32_t a3, uint32_t b0, uint32_t b1) {
    asm volatile(
        "mma.sync.aligned.m16n8k16.row.col.f32.f16.f16.f32 "
        "{%0,%1,%2,%3}, {%4,%5,%6,%7}, {%8,%9}, {%0,%1,%2,%3};"
        : "+f"(c[0]), "+f"(c[1]), "+f"(c[2]), "+f"(c[3])
        : "r"(a0), "r"(a1), "r"(a2), "r"(a3), "r"(b0), "r"(b1));
}
__device__ __forceinline__ float tanh_fast(float x) {
    float r;
    asm("tanh.approx.f32 %0, %1;" : "=f"(r) : "f"(x));
    return r;
}
__device__ __forceinline__ uint32_t swz(uint32_t bo) { return bo ^ ((bo >> 3) & 0x70); }

// ================== split-fp16 GEMM via mma.sync: C = A @ B^T ================
// 512 threads, 16 warps in 4x4 grid, warp tile 32 x (BN_/4).
// MODE 1: fp32 + bias   MODE 2: fp16 + bias   MODE 3: fp32 + bias, n<32 only
// PASSES: 1 = Ah*Bh | 2 = Ah*Bh + Al*Bh | 3 = Ah*Bh + Ah*Bl + Al*Bh
template<int ROWS>
__device__ __forceinline__ void load_tile_async(const __half* __restrict__ g,
                                                long row0, int ld, int k0,
                                                uint32_t sb, int tid) {
    #pragma unroll
    for (int t = 0; t < ROWS/64; t++) {
        int idx = tid + t * 512;
        int r = idx >> 3, cv = idx & 7;
        cp16(sb + swz((uint32_t)(r * 128 + cv * 16)),
             g + (row0 + r) * (long)ld + k0 + cv * 8);
    }
}

template<int MODE, int PASSES, int BN_>
__global__ __launch_bounds__(512, 1)
void gemm_mma(const __half* __restrict__ Ah, const __half* __restrict__ Al, int lda,
              const __half* __restrict__ Bh, const __half* __restrict__ Bl, int ldb,
              const float* __restrict__ bias,
              float* __restrict__ Cout, int ldc,
              __half* __restrict__ outh, int ldr,
              int K)
{
    constexpr int ATILE = 16384;
    constexpr int BTILE = BN_ * 128;
    constexpr int OFF_AL = ATILE;
    constexpr int OFF_BH = (PASSES >= 2) ? 2*ATILE : ATILE;
    constexpr int OFF_BL = OFF_BH + BTILE;
    constexpr int STAGE  = OFF_BH + ((PASSES == 3) ? 2*BTILE : BTILE);
    constexpr int WN = BN_ / 4;          // cols per warp (32 or 16)
    constexpr int NF = WN / 8;           // n8 fragments per warp (4 or 2)
    constexpr int NB = WN / 16;          // ldsm.x4 B loads per warp per ks (2 or 1)

    extern __shared__ char smem_raw[];
    uint32_t raw = smem_u32(smem_raw);
    const uint32_t sbase = (raw + 1023u) & ~1023u;

    const int tid  = threadIdx.x;
    const int wid  = tid >> 5, lane = tid & 31;
    const int warpM = wid & 3, warpN = wid >> 2;    // 4 x 4
    const long m0 = (long)blockIdx.y * 128;
    const int  n0 = blockIdx.x * BN_;

    float acc[2][NF][4];
    #pragma unroll
    for (int i = 0; i < 2; i++)
        #pragma unroll
        for (int j = 0; j < NF; j++)
            #pragma unroll
            for (int q = 0; q < 4; q++) acc[i][j][q] = 0.f;

    const int rowA0 = warpM * 32 + (lane & 7) + ((lane >> 3) & 1) * 8;
    const int khA   = (lane >> 4) & 1;
    const int rowB0 = warpN * WN + (lane & 7) + ((lane >> 4) & 1) * 8;
    const int khB   = (lane >> 3) & 1;

    const int NC = K / 64;

    auto issue = [&](int c) {
        uint32_t st = sbase + (uint32_t)(c % 3) * STAGE;
        int k0 = c * 64;
        load_tile_async<128>(Ah, m0, lda, k0, st, tid);
        if (PASSES >= 2) load_tile_async<128>(Al, m0, lda, k0, st + OFF_AL, tid);
        load_tile_async<BN_>(Bh, n0, ldb, k0, st + OFF_BH, tid);
        if (PASSES == 3) load_tile_async<BN_>(Bl, n0, ldb, k0, st + OFF_BL, tid);
        CP_COMMIT();
    };

    issue(0);
    if (NC > 1) issue(1);

    for (int c = 0; c < NC; c++) {
        if (c + 2 < NC)      { issue(c + 2); cp_wait<2>(); }
        else if (c + 1 < NC) { cp_wait<1>(); }
        else                 { cp_wait<0>(); }
        __syncthreads();

        uint32_t st = sbase + (uint32_t)(c % 3) * STAGE;
        #pragma unroll
        for (int ks = 0; ks < 4; ks++) {
            uint32_t ah[2][4], al[2][4], bh[NF][2], bl[NF][2];
            #pragma unroll
            for (int mi = 0; mi < 2; mi++) {
                uint32_t bo = swz((uint32_t)((rowA0 + mi*16) * 128 + ks*32 + khA*16));
                ldsm_x4(ah[mi][0], ah[mi][1], ah[mi][2], ah[mi][3], st + bo);
                if (PASSES >= 2)
                    ldsm_x4(al[mi][0], al[mi][1], al[mi][2], al[mi][3], st + OFF_AL + bo);
            }
            #pragma unroll
            for (int nb = 0; nb < NB; nb++) {
                uint32_t bo = swz((uint32_t)((rowB0 + nb*16) * 128 + ks*32 + khB*16));
                ldsm_x4(bh[nb*2][0], bh[nb*2][1], bh[nb*2+1][0], bh[nb*2+1][1],
                        st + OFF_BH + bo);
                if (PASSES == 3)
                    ldsm_x4(bl[nb*2][0], bl[nb*2][1], bl[nb*2+1][0], bl[nb*2+1][1],
                            st + OFF_BL + bo);
            }
            #pragma unroll
            for (int mi = 0; mi < 2; mi++)
                #pragma unroll
                for (int nf = 0; nf < NF; nf++)
                    mma16816(acc[mi][nf], ah[mi][0], ah[mi][1], ah[mi][2], ah[mi][3],
                             bh[nf][0], bh[nf][1]);
            if (PASSES == 3) {
                #pragma unroll
                for (int mi = 0; mi < 2; mi++)
                    #pragma unroll
                    for (int nf = 0; nf < NF; nf++)
                        mma16816(acc[mi][nf], ah[mi][0], ah[mi][1], ah[mi][2], ah[mi][3],
                                 bl[nf][0], bl[nf][1]);
            }
            if (PASSES >= 2) {
                #pragma unroll
                for (int mi = 0; mi < 2; mi++)
                    #pragma unroll
                    for (int nf = 0; nf < NF; nf++)
                        mma16816(acc[mi][nf], al[mi][0], al[mi][1], al[mi][2], al[mi][3],
                                 bh[nf][0], bh[nf][1]);
            }
        }
        __syncthreads();
    }

    const int g  = lane >> 2, tg = lane & 3;
    #pragma unroll
    for (int mi = 0; mi < 2; mi++) {
        #pragma unroll
        for (int h = 0; h < 2; h++) {
            long m = m0 + warpM * 32 + mi * 16 + h * 8 + g;
            #pragma unroll
            for (int nf = 0; nf < NF; nf++) {
                int n = n0 + warpN * WN + nf * 8 + tg * 2;
                if (MODE == 3 && n >= 32) continue;
                float2 bv = *reinterpret_cast<const float2*>(&bias[n]);
                float v0 = acc[mi][nf][h*2+0] + bv.x;
                float v1 = acc[mi][nf][h*2+1] + bv.y;
                if (MODE == 2) {
                    __half2 p;
                    p.x = __float2half_rn(v0);
                    p.y = __float2half_rn(v1);
                    *reinterpret_cast<__half2*>(&outh[m * (long)ldr + n]) = p;
                } else {
                    *reinterpret_cast<float2*>(&Cout[m * (long)ldc + n]) =
                        make_float2(v0, v1);
                }
            }
        }
    }
}

// ---------------- prep kernels -----------------------------------------------
__global__ void prep_at(const float* __restrict__ dt, const float* __restrict__ A,
                        float* __restrict__ At) {
    int t = blockIdx.x * blockDim.x + threadIdx.x;
    if (t < 4096) {
        int j = t >> 8, e = t & 255;
        At[t] = expf(expf(dt[j]) * A[e]);
    }
}

__global__ void prep_wred(const float* __restrict__ Wout, float* __restrict__ Wred) {
    int t = blockIdx.x * blockDim.x + threadIdx.x;
    if (t < DMOD * DST) {
        int m = t >> 4, s = t & 15;
        float sum = 0.f;
        #pragma unroll 8
        for (int r = 0; r < DINN / DST; r++)
            sum += Wout[(size_t)m * DINN + r * DST + s];
        Wred[t] = sum;
    }
}

__global__ void split_f32_v4(const float* __restrict__ src,
                             __half* __restrict__ hi,
                             __half* __restrict__ lo, long n4) {
    long t = (long)blockIdx.x * blockDim.x + threadIdx.x;
    if (t < n4) {
        float4 v = reinterpret_cast<const float4*>(src)[t];
        __half h0 = __float2half_rn(v.x), h1 = __float2half_rn(v.y);
        __half h2 = __float2half_rn(v.z), h3 = __float2half_rn(v.w);
        __half2 ha; ha.x = h0; ha.y = h1;
        __half2 hb; hb.x = h2; hb.y = h3;
        __half2 la, lb;
        la.x = __float2half_rn(v.x - __half2float(h0));
        la.y = __float2half_rn(v.y - __half2float(h1));
        lb.x = __float2half_rn(v.z - __half2float(h2));
        lb.y = __float2half_rn(v.w - __half2float(h3));
        reinterpret_cast<__half2*>(hi)[t*2]   = ha;
        reinterpret_cast<__half2*>(hi)[t*2+1] = hb;
        reinterpret_cast<__half2*>(lo)[t*2]   = la;
        reinterpret_cast<__half2*>(lo)[t*2+1] = lb;
    }
}

__global__ void split_hi_v4(const float* __restrict__ src,
                            __half* __restrict__ hi, long n4) {
    long t = (long)blockIdx.x * blockDim.x + threadIdx.x;
    if (t < n4) {
        float4 v = reinterpret_cast<const float4*>(src)[t];
        __half2 ha; ha.x = __float2half_rn(v.x); ha.y = __float2half_rn(v.y);
        __half2 hb; hb.x = __float2half_rn(v.z); hb.y = __float2half_rn(v.w);
        reinterpret_cast<__half2*>(hi)[t*2]   = ha;
        reinterpret_cast<__half2*>(hi)[t*2+1] = hb;
    }
}

// transpose + split: src [DINN, DMOD] -> th/tl [DMOD, DINN]
__global__ void transpose_split(const float* __restrict__ src,
                                __half* __restrict__ th,
                                __half* __restrict__ tl) {
    __shared__ float tile[32][33];
    int di0 = blockIdx.x * 32, dm0 = blockIdx.y * 32;
    int tx = threadIdx.x, ty = threadIdx.y;
    #pragma unroll
    for (int i = 0; i < 32; i += 8)
        tile[ty + i][tx] = src[(size_t)(di0 + ty + i) * DMOD + dm0 + tx];
    __syncthreads();
    #pragma unroll
    for (int i = 0; i < 32; i += 8) {
        float v = tile[tx][ty + i];
        __half h = __float2half_rn(v);
        size_t o = (size_t)(dm0 + ty + i) * DINN + di0 + tx;
        th[o] = h;
        tl[o] = __float2half_rn(v - __half2float(h));
    }
}

__global__ void prep_bconst(const float* __restrict__ Wout,
                            const float* __restrict__ b2,
                            const float* __restrict__ bout,
                            float* __restrict__ bc) {
    int n = blockIdx.x * 8 + (threadIdx.x >> 5);
    int lane = threadIdx.x & 31;
    float s = 0.f;
    for (int k = lane; k < DINN; k += 32)
        s = fmaf(Wout[(size_t)n * DINN + k], b2[k], s);
    #pragma unroll
    for (int o = 16; o; o >>= 1) s += __shfl_xor_sync(0xffffffffu, s, o);
    if (lane == 0) bc[n] = s + bout[n];
}

__global__ void prep_wx(const float* __restrict__ Wx, __half* __restrict__ o) {
    int t = blockIdx.x * blockDim.x + threadIdx.x;
    if (t < 128 * DINN) {
        int n = t / DINN, k = t % DINN;
        o[t] = __float2half_rn((n < 32) ? Wx[(size_t)n * DINN + k] : 0.f);
    }
}

// ---------------- depthwise causal conv (K=4) + SiLU (scalar, coalesced) -----
__global__ void conv_silu(const __half* __restrict__ xi,
                          const float* __restrict__ w,
                          const float* __restrict__ cb,
                          __half* __restrict__ xs)
{
    long t = (long)blockIdx.x * blockDim.x + threadIdx.x;
    if (t >= (long)MROWS * DINN) return;
    int  c  = (int)(t & (DINN - 1));
    long bl = t >> 11;
    int  l  = (int)(bl & (LSEQ - 1));
    long row0 = bl - l;

    float4 wv = *reinterpret_cast<const float4*>(&w[c * 4]);
    float acc = cb[c];
    const float wk[4] = {wv.x, wv.y, wv.z, wv.w};
    #pragma unroll
    for (int k = 0; k < KCONV; k++) {
        int ll = l - (KCONV - 1) + k;
        if (ll >= 0)
            acc = fmaf(__half2float(xi[(size_t)(row0 + ll) * DINN + c]), wk[k], acc);
    }
    float s = 1.f / (1.f + expf(-acc));
    xs[t] = __float2half_rn(acc * s);
}

// ---------------- sequential nonlinear scan ----------------------------------
__global__ void scan_kernel(const float* __restrict__ bc,
                            const float* __restrict__ At,
                            float* __restrict__ hs)
{
    const int b = blockIdx.x;
    const int i = threadIdx.x;
    const unsigned mask = 0xffffu;
    __shared__ float sAt[16*16*16];
    __shared__ float sBC[64*32];

    for (int t = i; t < 4096/4; t += 16)
        reinterpret_cast<float4*>(sAt)[t] = reinterpret_cast<const float4*>(At)[t];

    const float* bcb = bc + (size_t)b*LSEQ*32;
    float*       hsb = hs + (size_t)b*LSEQ*DST;
    float h = 0.f;

    for (int l0 = 0; l0 < LSEQ; l0 += 64) {
        __syncwarp(mask);
        const float4* src = reinterpret_cast<const float4*>(bcb + (size_t)l0*32);
        for (int t = i; t < 64*32/4; t += 16)
            reinterpret_cast<float4*>(sBC)[t] = src[t];
        __syncwarp(mask);
        for (int ll = 0; ll < 64; ll++) {
            int l = l0 + ll;
            float Bv = sBC[ll*32 + i];
            float Cv = sBC[ll*32 + 16 + i];
            const float* Ar = &sAt[((l & 15) << 8) + (i << 4)];
            float a0 = Cv, a1 = 0.f, a2 = 0.f, a3 = Bv * h;
            #pragma unroll
            for (int j = 0; j < 16; j += 4) {
                a0 = fmaf(Ar[j+0], __shfl_sync(mask, h, j+0), a0);
                a1 = fmaf(Ar[j+1], __shfl_sync(mask, h, j+1), a1);
                a2 = fmaf(Ar[j+2], __shfl_sync(mask, h, j+2), a2);
                a3 = fmaf(Ar[j+3], __shfl_sync(mask, h, j+3), a3);
            }
            h = tanh_fast((a0 + a1) + (a2 + a3));
            hsb[(size_t)l*DST + i] = h;
        }
    }
}

// ---------------- rank-16 update: out += hs @ Wred^T (fp32) ------------------
__global__ void rank16_add(float* __restrict__ out,
                           const float* __restrict__ hs,
                           const float* __restrict__ Wred) {
    int m = blockIdx.x;
    int t = threadIdx.x;
    __shared__ float sh[16];
    if (t < 16) sh[t] = hs[(size_t)m * 16 + t];
    __syncthreads();
    float4 v = reinterpret_cast<float4*>(out)[(size_t)m * 256 + t];
    int n0 = t * 4;
    #pragma unroll
    for (int s = 0; s < 16; s++) {
        float hv = sh[s];
        v.x = fmaf(hv, Wred[(n0+0)*16 + s], v.x);
        v.y = fmaf(hv, Wred[(n0+1)*16 + s], v.y);
        v.z = fmaf(hv, Wred[(n0+2)*16 + s], v.z);
        v.w = fmaf(hv, Wred[(n0+3)*16 + s], v.w);
    }
    reinterpret_cast<float4*>(out)[(size_t)m * 256 + t] = v;
}

// ---------------- stream / event singletons ----------------------------------
static cudaStream_t side_stream() {
    static cudaStream_t s = []() {
        cudaStream_t t;
        cudaStreamCreateWithFlags(&t, cudaStreamNonBlocking);
        return t;
    }();
    return s;
}
static cudaEvent_t ev(int i) {
    static cudaEvent_t e[4] = {nullptr, nullptr, nullptr, nullptr};
    if (!e[0])
        for (int k = 0; k < 4; k++)
            cudaEventCreateWithFlags(&e[k], cudaEventDisableTiming);
    return e[i];
}

// ---------------- launcher ----------------------------------------------------
extern "C" void kernel_launch(void* const* d_in, const int* in_sizes, int n_in,
                              void* d_out, int out_size)
{
    const float* x      = (const float*)d_in[0];
    const float* W_in   = (const float*)d_in[1];
    const float* b_in   = (const float*)d_in[2];
    const float* conv_w = (const float*)d_in[3];
    const float* conv_b = (const float*)d_in[4];
    const float* W_x    = (const float*)d_in[5];
    const float* b_x    = (const float*)d_in[6];
    const float* dt     = (const float*)d_in[7];
    const float* A      = (const float*)d_in[8];
    const float* W_out  = (const float*)d_in[10];
    const float* b_out  = (const float*)d_in[11];
    float* out = (float*)d_out;

    float *bcv, *hsp, *Atp, *Wred, *bconst, *zerov;
    __half *xib, *xsb, *xh, *xl, *winh, *winTh, *winTl, *woh, *wol, *wcombh, *wxh;
    cudaGetSymbolAddress((void**)&xib,    g_xib);
    cudaGetSymbolAddress((void**)&xsb,    g_xsb);
    cudaGetSymbolAddress((void**)&bcv,    g_bc);
    cudaGetSymbolAddress((void**)&hsp,    g_hs);
    cudaGetSymbolAddress((void**)&Atp,    g_At);
    cudaGetSymbolAddress((void**)&Wred,   g_Wred);
    cudaGetSymbolAddress((void**)&bconst, g_bconst);
    cudaGetSymbolAddress((void**)&zerov,  g_zero);
    cudaGetSymbolAddress((void**)&xh,     g_xh);
    cudaGetSymbolAddress((void**)&xl,     g_xl);
    cudaGetSymbolAddress((void**)&winh,   g_winh);
    cudaGetSymbolAddress((void**)&winTh,  g_winTh);
    cudaGetSymbolAddress((void**)&winTl,  g_winTl);
    cudaGetSymbolAddress((void**)&woh,    g_woh);
    cudaGetSymbolAddress((void**)&wol,    g_wol);
    cudaGetSymbolAddress((void**)&wcombh, g_wcombh);
    cudaGetSymbolAddress((void**)&wxh,    g_wxh);

    const int SM_XI   = 3 * (2 * 16384) + 1024;               // P1 BN128
    const int SM_BC   = 3 * (16384 + 64*128) + 1024;          // P1 BN64
    const int SM_P364 = 3 * (2 * 16384 + 2 * 64*128) + 1024;  // P3 BN64 (Wcomb)
    const int SM_P2128= 3 * (3 * 16384) + 1024;               // P2 BN128 (out)
    cudaFuncSetAttribute(gemm_mma<2,1,128>, cudaFuncAttributeMaxDynamicSharedMemorySize, SM_XI);
    cudaFuncSetAttribute(gemm_mma<3,1,64>,  cudaFuncAttributeMaxDynamicSharedMemorySize, SM_BC);
    cudaFuncSetAttribute(gemm_mma<2,3,64>,  cudaFuncAttributeMaxDynamicSharedMemorySize, SM_P364);
    cudaFuncSetAttribute(gemm_mma<1,2,128>, cudaFuncAttributeMaxDynamicSharedMemorySize, SM_P2128);

    cudaStream_t sd = side_stream();
    cudaEvent_t e_fork = ev(0), e_x = ev(1), e_hs = ev(2), e_done = ev(3);

    // ---- fork side stream at capture start ----
    cudaEventRecord(e_fork, 0);
    cudaStreamWaitEvent(sd, e_fork, 0);

    // ==== stream 0: xi chain (gemm1a kept at launch #4 for profiling) ====
    split_f32_v4<<<(int)(((long)MROWS*DMOD/4 + 255)/256), 256>>>(x, xh, xl, (long)MROWS*DMOD/4);
    cudaEventRecord(e_x, 0);
    split_hi_v4<<<(int)(((long)DINN*DMOD/4 + 255)/256), 256>>>(W_in, winh, (long)DINN*DMOD/4);
    prep_at<<<16, 256>>>(dt, A, Atp);
    gemm_mma<2,1,128><<<dim3(DINN/128, MROWS/128), 512, SM_XI>>>(      // launch #4
        xh, nullptr, DMOD, winh, nullptr, DMOD, b_in,
        nullptr, 0, xib, DINN, DMOD);
    conv_silu<<<(MROWS*DINN)/256, 256>>>(xib, conv_w, conv_b, xsb);
    prep_wx<<<(128*DINN + 255)/256, 256>>>(W_x, wxh);
    gemm_mma<3,1,64><<<dim3(1, MROWS/128), 512, SM_BC>>>(
        xsb, nullptr, DINN, wxh, nullptr, DINN, b_x,
        bcv, 32, nullptr, 0, DINN);
    scan_kernel<<<BATCH, 16>>>(bcv, Atp, hsp);
    cudaEventRecord(e_hs, 0);

    // ==== side stream: output chain ====
    split_f32_v4<<<(int)(((long)DMOD*DINN/4 + 255)/256), 256, 0, sd>>>(
        W_out, woh, wol, (long)DMOD*DINN/4);
    transpose_split<<<dim3(DINN/32, DMOD/32), dim3(32, 8), 0, sd>>>(
        W_in + (size_t)DINN*DMOD, winTh, winTl);
    prep_wred<<<64, 256, 0, sd>>>(W_out, Wred);
    prep_bconst<<<DMOD/8, 256, 0, sd>>>(W_out, b_in + DINN, b_out, bconst);

    // Wcomb = Wout @ Win2 (1024x1024, K=2048), 3-pass, fp16-hi out
    gemm_mma<2,3,64><<<dim3(DMOD/64, DMOD/128), 512, SM_P364, sd>>>(
        woh, wol, DINN, winTh, winTl, DINN, zerov,
        nullptr, 0, wcombh, DMOD, DINN);
    // out = x @ Wcomb^T + bconst (2-pass: x split, Wcomb hi)
    cudaStreamWaitEvent(sd, e_x, 0);
    gemm_mma<1,2,128><<<dim3(DMOD/128, MROWS/128), 512, SM_P2128, sd>>>(
        xh, xl, DMOD, wcombh, nullptr, DMOD, bconst,
        out, DMOD, nullptr, 0, DMOD);
    // out += hs @ Wred^T
    cudaStreamWaitEvent(sd, e_hs, 0);
    rank16_add<<<MROWS, 256, 0, sd>>>(out, hsp, Wred);
    cudaEventRecord(e_done, sd);

    // ---- join side stream before capture ends ----
    cudaStreamWaitEvent(0, e_done, 0);
}

// round 10
// speedup vs baseline: 1.2491x; 1.1266x over previous
#include <cuda_runtime.h>
#include <cuda_bf16.h>
#include <math.h>
#include <stdint.h>

#define BATCH 4
#define LSEQ  2048
#define DMOD  1024
#define DST   16
#define KCONV 4
#define DINN  2048
#define MROWS (BATCH*LSEQ)   /* 8192 */

// ---------------- scratch (device globals) -----------------------------------
__device__ __align__(128) __nv_bfloat16 g_xib[(size_t)MROWS * DINN];
__device__ __align__(128) __nv_bfloat16 g_xsb[(size_t)MROWS * DINN];
__device__ __align__(128) float g_bc[(size_t)MROWS * 32];
__device__ __align__(128) float g_hs[(size_t)MROWS * DST];
__device__ __align__(128) float g_At[16*16*16];
__device__ __align__(128) float g_Wred[DMOD*DST];
__device__ __align__(128) float g_bconst[DMOD];
__device__ __align__(128) float g_zero[DMOD];
__device__ __align__(128) __nv_bfloat16 g_xh[(size_t)MROWS*DMOD], g_xl[(size_t)MROWS*DMOD];
__device__ __align__(128) __nv_bfloat16 g_winh[(size_t)DINN*DMOD];
__device__ __align__(128) __nv_bfloat16 g_winTh[(size_t)DMOD*DINN], g_winTl[(size_t)DMOD*DINN];
__device__ __align__(128) __nv_bfloat16 g_woh[(size_t)DMOD*DINN], g_wol[(size_t)DMOD*DINN];
__device__ __align__(128) __nv_bfloat16 g_wcombh[(size_t)DMOD*DMOD], g_wcombl[(size_t)DMOD*DMOD];
__device__ __align__(128) __nv_bfloat16 g_wxh[(size_t)128*DINN];

// ============================ PTX helpers (arch-agnostic) ====================
__device__ __forceinline__ uint32_t smem_u32(const void* p) {
    uint32_t a;
    asm("{ .reg .u64 t; cvta.to.shared.u64 t, %1; cvt.u32.u64 %0, t; }"
        : "=r"(a) : "l"(p));
    return a;
}
__device__ __forceinline__ void cp16(uint32_t s, const void* g) {
    asm volatile("cp.async.cg.shared.global [%0], [%1], 16;" :: "r"(s), "l"(g));
}
#define CP_COMMIT() asm volatile("cp.async.commit_group;" ::: "memory")
template<int N> __device__ __forceinline__ void cp_wait() {
    asm volatile("cp.async.wait_group %0;" :: "n"(N) : "memory");
}
__device__ __forceinline__ void ldsm_x4(uint32_t& r0, uint32_t& r1,
                                        uint32_t& r2, uint32_t& r3, uint32_t a) {
    asm volatile("ldmatrix.sync.aligned.m8n8.x4.shared.b16 {%0,%1,%2,%3}, [%4];"
                 : "=r"(r0), "=r"(r1), "=r"(r2), "=r"(r3) : "r"(a));
}
__device__ __forceinline__ void mma16816(float* c,
    uint32_t a0, uint32_t a1, uint32_t a2, uint32_t a3, uint32_t b0, uint32_t b1) {
    asm volatile(
        "mma.sync.aligned.m16n8k16.row.col.f32.bf16.bf16.f32 "
        "{%0,%1,%2,%3}, {%4,%5,%6,%7}, {%8,%9}, {%0,%1,%2,%3};"
        : "+f"(c[0]), "+f"(c[1]), "+f"(c[2]), "+f"(c[3])
        : "r"(a0), "r"(a1), "r"(a2), "r"(a3), "r"(b0), "r"(b1));
}
__device__ __forceinline__ float tanh_fast(float x) {
    float r;
    asm("tanh.approx.f32 %0, %1;" : "=f"(r) : "f"(x));
    return r;
}
__device__ __forceinline__ uint32_t swz(uint32_t bo) { return bo ^ ((bo >> 3) & 0x70); }

// 256-thread tile loader (ROWS x 64 bf16 = ROWS x 128B, SW128 swizzled)
template<int ROWS>
__device__ __forceinline__ void load_tile_async(const __nv_bfloat16* __restrict__ g,
                                                long row0, int ld, int k0,
                                                uint32_t sb, int tid) {
    #pragma unroll
    for (int t = 0; t < ROWS/32; t++) {
        int idx = tid + t * 256;
        int r = idx >> 3, cv = idx & 7;
        cp16(sb + swz((uint32_t)(r * 128 + cv * 16)),
             g + (row0 + r) * (long)ld + k0 + cv * 8);
    }
}

// ============== BIG-TILE GEMM: CTA 128x256, 8 warps 2x4, warp 64x64 ==========
// MODE 1: fp32 + bias out    MODE 2: bf16 + bias out
// PASSES 1: Ah*Bh            PASSES 3: Ah*Bh + Ah*Bl + Al*Bh
// STAGES: cp.async pipeline depth (2 or 3)
template<int MODE, int PASSES, int STAGES>
__global__ __launch_bounds__(256, 1)
void gemm_big(const __nv_bfloat16* __restrict__ Ah, const __nv_bfloat16* __restrict__ Al, int lda,
              const __nv_bfloat16* __restrict__ Bh, const __nv_bfloat16* __restrict__ Bl, int ldb,
              const float* __restrict__ bias,
              float* __restrict__ Cout, int ldc,
              __nv_bfloat16* __restrict__ outh, int ldr,
              int K)
{
    constexpr int ATILE = 16384;             // 128 x 128B
    constexpr int BTILE = 32768;             // 256 x 128B
    constexpr int OFF_AL = ATILE;
    constexpr int OFF_BH = (PASSES == 3) ? 2*ATILE : ATILE;
    constexpr int OFF_BL = OFF_BH + BTILE;
    constexpr int STAGE  = OFF_BH + ((PASSES == 3) ? 2*BTILE : BTILE);

    extern __shared__ char smem_raw[];
    uint32_t raw = smem_u32(smem_raw);
    const uint32_t sbase = (raw + 1023u) & ~1023u;

    const int tid  = threadIdx.x;
    const int wid  = tid >> 5, lane = tid & 31;
    const int warpM = wid & 1, warpN = wid >> 1;       // 2 x 4
    const long m0 = (long)blockIdx.y * 128;
    const int  n0 = blockIdx.x * 256;

    float acc[4][8][4];
    #pragma unroll
    for (int i = 0; i < 4; i++)
        #pragma unroll
        for (int j = 0; j < 8; j++)
            #pragma unroll
            for (int q = 0; q < 4; q++) acc[i][j][q] = 0.f;

    const int rowA0 = warpM * 64 + (lane & 7) + ((lane >> 3) & 1) * 8;   // + mi*16
    const int khA   = (lane >> 4) & 1;
    const int rowB0 = warpN * 64 + (lane & 7) + ((lane >> 4) & 1) * 8;   // + nb*16
    const int khB   = (lane >> 3) & 1;

    const int NC = K / 64;

    auto issue = [&](int c) {
        uint32_t st = sbase + (uint32_t)(c % STAGES) * STAGE;
        int k0 = c * 64;
        load_tile_async<128>(Ah, m0, lda, k0, st, tid);
        if (PASSES == 3) load_tile_async<128>(Al, m0, lda, k0, st + OFF_AL, tid);
        load_tile_async<256>(Bh, n0, ldb, k0, st + OFF_BH, tid);
        if (PASSES == 3) load_tile_async<256>(Bl, n0, ldb, k0, st + OFF_BL, tid);
        CP_COMMIT();
    };

    issue(0);
    if (STAGES == 3 && NC > 1) issue(1);

    for (int c = 0; c < NC; c++) {
        if (STAGES == 3) {
            if (c + 2 < NC)      { issue(c + 2); cp_wait<2>(); }
            else if (c + 1 < NC) { cp_wait<1>(); }
            else                 { cp_wait<0>(); }
        } else {
            if (c + 1 < NC)      { issue(c + 1); cp_wait<1>(); }
            else                 { cp_wait<0>(); }
        }
        __syncthreads();

        uint32_t st = sbase + (uint32_t)(c % STAGES) * STAGE;
        #pragma unroll
        for (int ks = 0; ks < 4; ks++) {
            uint32_t ah[4][4], al[4][4], bh[8][2], bl[8][2];
            #pragma unroll
            for (int mi = 0; mi < 4; mi++) {
                uint32_t bo = swz((uint32_t)((rowA0 + mi*16) * 128 + ks*32 + khA*16));
                ldsm_x4(ah[mi][0], ah[mi][1], ah[mi][2], ah[mi][3], st + bo);
                if (PASSES == 3)
                    ldsm_x4(al[mi][0], al[mi][1], al[mi][2], al[mi][3], st + OFF_AL + bo);
            }
            #pragma unroll
            for (int nb = 0; nb < 4; nb++) {
                uint32_t bo = swz((uint32_t)((rowB0 + nb*16) * 128 + ks*32 + khB*16));
                ldsm_x4(bh[nb*2][0], bh[nb*2][1], bh[nb*2+1][0], bh[nb*2+1][1],
                        st + OFF_BH + bo);
                if (PASSES == 3)
                    ldsm_x4(bl[nb*2][0], bl[nb*2][1], bl[nb*2+1][0], bl[nb*2+1][1],
                            st + OFF_BL + bo);
            }
            #pragma unroll
            for (int mi = 0; mi < 4; mi++)
                #pragma unroll
                for (int nf = 0; nf < 8; nf++)
                    mma16816(acc[mi][nf], ah[mi][0], ah[mi][1], ah[mi][2], ah[mi][3],
                             bh[nf][0], bh[nf][1]);
            if (PASSES == 3) {
                #pragma unroll
                for (int mi = 0; mi < 4; mi++)
                    #pragma unroll
                    for (int nf = 0; nf < 8; nf++)
                        mma16816(acc[mi][nf], ah[mi][0], ah[mi][1], ah[mi][2], ah[mi][3],
                                 bl[nf][0], bl[nf][1]);
                #pragma unroll
                for (int mi = 0; mi < 4; mi++)
                    #pragma unroll
                    for (int nf = 0; nf < 8; nf++)
                        mma16816(acc[mi][nf], al[mi][0], al[mi][1], al[mi][2], al[mi][3],
                                 bh[nf][0], bh[nf][1]);
            }
        }
        __syncthreads();
    }

    const int g  = lane >> 2, tg = lane & 3;
    #pragma unroll
    for (int mi = 0; mi < 4; mi++) {
        #pragma unroll
        for (int h = 0; h < 2; h++) {
            long m = m0 + warpM * 64 + mi * 16 + h * 8 + g;
            #pragma unroll
            for (int nf = 0; nf < 8; nf++) {
                int n = n0 + warpN * 64 + nf * 8 + tg * 2;
                float2 bv = *reinterpret_cast<const float2*>(&bias[n]);
                float v0 = acc[mi][nf][h*2+0] + bv.x;
                float v1 = acc[mi][nf][h*2+1] + bv.y;
                if (MODE == 2) {
                    __nv_bfloat162 p;
                    p.x = __float2bfloat16(v0);
                    p.y = __float2bfloat16(v1);
                    *reinterpret_cast<__nv_bfloat162*>(&outh[m * (long)ldr + n]) = p;
                } else {
                    *reinterpret_cast<float2*>(&Cout[m * (long)ldc + n]) =
                        make_float2(v0, v1);
                }
            }
        }
    }
}

// ============== small GEMM (R6 config): CTA 128xBN, 8 warps 4x2 ==============
// MODE 0: split-bf16 out + bias   MODE 3: fp32 + bias, n<32 only
template<int MODE, int PASSES, int BN_>
__global__ __launch_bounds__(256, 1)
void gemm_mma(const __nv_bfloat16* __restrict__ Ah, const __nv_bfloat16* __restrict__ Al, int lda,
              const __nv_bfloat16* __restrict__ Bh, const __nv_bfloat16* __restrict__ Bl, int ldb,
              const float* __restrict__ bias,
              float* __restrict__ Cout, int ldc,
              __nv_bfloat16* __restrict__ outh, __nv_bfloat16* __restrict__ outl, int ldr,
              int K)
{
    constexpr int ATILE = 16384;
    constexpr int BTILE = BN_ * 128;
    constexpr int OFF_AL = ATILE;
    constexpr int OFF_BH = (PASSES == 3) ? 2*ATILE : ATILE;
    constexpr int OFF_BL = OFF_BH + BTILE;
    constexpr int STAGE  = OFF_BH + ((PASSES == 3) ? 2*BTILE : BTILE);
    constexpr int NF = BN_ / 16;
    constexpr int NB = BN_ / 32;

    extern __shared__ char smem_raw[];
    uint32_t raw = smem_u32(smem_raw);
    const uint32_t sbase = (raw + 1023u) & ~1023u;

    const int tid  = threadIdx.x;
    const int wid  = tid >> 5, lane = tid & 31;
    const int warpM = wid & 3, warpN = wid >> 2;
    const long m0 = (long)blockIdx.y * 128;
    const int  n0 = blockIdx.x * BN_;

    float acc[2][NF][4];
    #pragma unroll
    for (int i = 0; i < 2; i++)
        #pragma unroll
        for (int j = 0; j < NF; j++)
            #pragma unroll
            for (int q = 0; q < 4; q++) acc[i][j][q] = 0.f;

    const int rowA0 = warpM * 32 + (lane & 7) + ((lane >> 3) & 1) * 8;
    const int khA   = (lane >> 4) & 1;
    const int rowB0 = warpN * (BN_/2) + (lane & 7) + ((lane >> 4) & 1) * 8;
    const int khB   = (lane >> 3) & 1;

    const int NC = K / 64;

    auto issue = [&](int c) {
        uint32_t st = sbase + (uint32_t)(c % 3) * STAGE;
        int k0 = c * 64;
        load_tile_async<128>(Ah, m0, lda, k0, st, tid);
        if (PASSES == 3) load_tile_async<128>(Al, m0, lda, k0, st + OFF_AL, tid);
        load_tile_async<BN_>(Bh, n0, ldb, k0, st + OFF_BH, tid);
        if (PASSES == 3) load_tile_async<BN_>(Bl, n0, ldb, k0, st + OFF_BL, tid);
        CP_COMMIT();
    };

    issue(0);
    if (NC > 1) issue(1);

    for (int c = 0; c < NC; c++) {
        if (c + 2 < NC)      { issue(c + 2); cp_wait<2>(); }
        else if (c + 1 < NC) { cp_wait<1>(); }
        else                 { cp_wait<0>(); }
        __syncthreads();

        uint32_t st = sbase + (uint32_t)(c % 3) * STAGE;
        #pragma unroll
        for (int ks = 0; ks < 4; ks++) {
            uint32_t ah[2][4], al[2][4], bh[NF][2], bl[NF][2];
            #pragma unroll
            for (int mi = 0; mi < 2; mi++) {
                uint32_t bo = swz((uint32_t)((rowA0 + mi*16) * 128 + ks*32 + khA*16));
                ldsm_x4(ah[mi][0], ah[mi][1], ah[mi][2], ah[mi][3], st + bo);
                if (PASSES == 3)
                    ldsm_x4(al[mi][0], al[mi][1], al[mi][2], al[mi][3], st + OFF_AL + bo);
            }
            #pragma unroll
            for (int nb = 0; nb < NB; nb++) {
                uint32_t bo = swz((uint32_t)((rowB0 + nb*16) * 128 + ks*32 + khB*16));
                ldsm_x4(bh[nb*2][0], bh[nb*2][1], bh[nb*2+1][0], bh[nb*2+1][1],
                        st + OFF_BH + bo);
                if (PASSES == 3)
                    ldsm_x4(bl[nb*2][0], bl[nb*2][1], bl[nb*2+1][0], bl[nb*2+1][1],
                            st + OFF_BL + bo);
            }
            #pragma unroll
            for (int mi = 0; mi < 2; mi++)
                #pragma unroll
                for (int nf = 0; nf < NF; nf++)
                    mma16816(acc[mi][nf], ah[mi][0], ah[mi][1], ah[mi][2], ah[mi][3],
                             bh[nf][0], bh[nf][1]);
            if (PASSES == 3) {
                #pragma unroll
                for (int mi = 0; mi < 2; mi++)
                    #pragma unroll
                    for (int nf = 0; nf < NF; nf++)
                        mma16816(acc[mi][nf], ah[mi][0], ah[mi][1], ah[mi][2], ah[mi][3],
                                 bl[nf][0], bl[nf][1]);
                #pragma unroll
                for (int mi = 0; mi < 2; mi++)
                    #pragma unroll
                    for (int nf = 0; nf < NF; nf++)
                        mma16816(acc[mi][nf], al[mi][0], al[mi][1], al[mi][2], al[mi][3],
                                 bh[nf][0], bh[nf][1]);
            }
        }
        __syncthreads();
    }

    const int g  = lane >> 2, tg = lane & 3;
    #pragma unroll
    for (int mi = 0; mi < 2; mi++) {
        #pragma unroll
        for (int h = 0; h < 2; h++) {
            long m = m0 + warpM * 32 + mi * 16 + h * 8 + g;
            #pragma unroll
            for (int nf = 0; nf < NF; nf++) {
                int n = n0 + warpN * (BN_/2) + nf * 8 + tg * 2;
                if (MODE == 3 && n >= 32) continue;
                float2 bv = *reinterpret_cast<const float2*>(&bias[n]);
                float v0 = acc[mi][nf][h*2+0] + bv.x;
                float v1 = acc[mi][nf][h*2+1] + bv.y;
                if (MODE == 0) {
                    __nv_bfloat16 h0 = __float2bfloat16(v0);
                    __nv_bfloat16 h1 = __float2bfloat16(v1);
                    __nv_bfloat16 l0 = __float2bfloat16(v0 - __bfloat162float(h0));
                    __nv_bfloat16 l1 = __float2bfloat16(v1 - __bfloat162float(h1));
                    long o = m * (long)ldr + n;
                    __nv_bfloat162 ph; ph.x = h0; ph.y = h1;
                    __nv_bfloat162 pl; pl.x = l0; pl.y = l1;
                    *reinterpret_cast<__nv_bfloat162*>(&outh[o]) = ph;
                    *reinterpret_cast<__nv_bfloat162*>(&outl[o]) = pl;
                } else {
                    *reinterpret_cast<float2*>(&Cout[m * (long)ldc + n]) =
                        make_float2(v0, v1);
                }
            }
        }
    }
}

// ---------------- prep kernels -----------------------------------------------
__global__ void prep_at(const float* __restrict__ dt, const float* __restrict__ A,
                        float* __restrict__ At) {
    int t = blockIdx.x * blockDim.x + threadIdx.x;
    if (t < 4096) {
        int j = t >> 8, e = t & 255;
        At[t] = expf(expf(dt[j]) * A[e]);
    }
}

__global__ void prep_wred(const float* __restrict__ Wout, float* __restrict__ Wred) {
    int t = blockIdx.x * blockDim.x + threadIdx.x;
    if (t < DMOD * DST) {
        int m = t >> 4, s = t & 15;
        float sum = 0.f;
        #pragma unroll 8
        for (int r = 0; r < DINN / DST; r++)
            sum += Wout[(size_t)m * DINN + r * DST + s];
        Wred[t] = sum;
    }
}

__global__ void split_f32_v4(const float* __restrict__ src,
                             __nv_bfloat16* __restrict__ hi,
                             __nv_bfloat16* __restrict__ lo, long n4) {
    long t = (long)blockIdx.x * blockDim.x + threadIdx.x;
    if (t < n4) {
        float4 v = reinterpret_cast<const float4*>(src)[t];
        __nv_bfloat16 h0 = __float2bfloat16(v.x), h1 = __float2bfloat16(v.y);
        __nv_bfloat16 h2 = __float2bfloat16(v.z), h3 = __float2bfloat16(v.w);
        __nv_bfloat162 ha; ha.x = h0; ha.y = h1;
        __nv_bfloat162 hb; hb.x = h2; hb.y = h3;
        __nv_bfloat162 la, lb;
        la.x = __float2bfloat16(v.x - __bfloat162float(h0));
        la.y = __float2bfloat16(v.y - __bfloat162float(h1));
        lb.x = __float2bfloat16(v.z - __bfloat162float(h2));
        lb.y = __float2bfloat16(v.w - __bfloat162float(h3));
        reinterpret_cast<__nv_bfloat162*>(hi)[t*2]   = ha;
        reinterpret_cast<__nv_bfloat162*>(hi)[t*2+1] = hb;
        reinterpret_cast<__nv_bfloat162*>(lo)[t*2]   = la;
        reinterpret_cast<__nv_bfloat162*>(lo)[t*2+1] = lb;
    }
}

__global__ void split_hi_v4(const float* __restrict__ src,
                            __nv_bfloat16* __restrict__ hi, long n4) {
    long t = (long)blockIdx.x * blockDim.x + threadIdx.x;
    if (t < n4) {
        float4 v = reinterpret_cast<const float4*>(src)[t];
        __nv_bfloat162 ha; ha.x = __float2bfloat16(v.x); ha.y = __float2bfloat16(v.y);
        __nv_bfloat162 hb; hb.x = __float2bfloat16(v.z); hb.y = __float2bfloat16(v.w);
        reinterpret_cast<__nv_bfloat162*>(hi)[t*2]   = ha;
        reinterpret_cast<__nv_bfloat162*>(hi)[t*2+1] = hb;
    }
}

// transpose + split: src [DINN, DMOD] -> th/tl [DMOD, DINN]
__global__ void transpose_split(const float* __restrict__ src,
                                __nv_bfloat16* __restrict__ th,
                                __nv_bfloat16* __restrict__ tl) {
    __shared__ float tile[32][33];
    int di0 = blockIdx.x * 32, dm0 = blockIdx.y * 32;
    int tx = threadIdx.x, ty = threadIdx.y;
    #pragma unroll
    for (int i = 0; i < 32; i += 8)
        tile[ty + i][tx] = src[(size_t)(di0 + ty + i) * DMOD + dm0 + tx];
    __syncthreads();
    #pragma unroll
    for (int i = 0; i < 32; i += 8) {
        float v = tile[tx][ty + i];
        __nv_bfloat16 h = __float2bfloat16(v);
        size_t o = (size_t)(dm0 + ty + i) * DINN + di0 + tx;
        th[o] = h;
        tl[o] = __float2bfloat16(v - __bfloat162float(h));
    }
}

__global__ void prep_bconst(const float* __restrict__ Wout,
                            const float* __restrict__ b2,
                            const float* __restrict__ bout,
                            float* __restrict__ bc) {
    int n = blockIdx.x * 8 + (threadIdx.x >> 5);
    int lane = threadIdx.x & 31;
    float s = 0.f;
    for (int k = lane; k < DINN; k += 32)
        s = fmaf(Wout[(size_t)n * DINN + k], b2[k], s);
    #pragma unroll
    for (int o = 16; o; o >>= 1) s += __shfl_xor_sync(0xffffffffu, s, o);
    if (lane == 0) bc[n] = s + bout[n];
}

__global__ void prep_wx(const float* __restrict__ Wx, __nv_bfloat16* __restrict__ o) {
    int t = blockIdx.x * blockDim.x + threadIdx.x;
    if (t < 128 * DINN) {
        int n = t / DINN, k = t % DINN;
        o[t] = __float2bfloat16((n < 32) ? Wx[(size_t)n * DINN + k] : 0.f);
    }
}

// ---------------- depthwise causal conv (K=4) + SiLU (scalar, coalesced) -----
__global__ void conv_silu(const __nv_bfloat16* __restrict__ xi,
                          const float* __restrict__ w,
                          const float* __restrict__ cb,
                          __nv_bfloat16* __restrict__ xs)
{
    long t = (long)blockIdx.x * blockDim.x + threadIdx.x;
    if (t >= (long)MROWS * DINN) return;
    int  c  = (int)(t & (DINN - 1));
    long bl = t >> 11;
    int  l  = (int)(bl & (LSEQ - 1));
    long row0 = bl - l;

    float4 wv = *reinterpret_cast<const float4*>(&w[c * 4]);
    float acc = cb[c];
    const float wk[4] = {wv.x, wv.y, wv.z, wv.w};
    #pragma unroll
    for (int k = 0; k < KCONV; k++) {
        int ll = l - (KCONV - 1) + k;
        if (ll >= 0)
            acc = fmaf(__bfloat162float(xi[(size_t)(row0 + ll) * DINN + c]), wk[k], acc);
    }
    float s = 1.f / (1.f + expf(-acc));
    xs[t] = __float2bfloat16(acc * s);
}

// ---------------- sequential nonlinear scan ----------------------------------
__global__ void scan_kernel(const float* __restrict__ bc,
                            const float* __restrict__ At,
                            float* __restrict__ hs)
{
    const int b = blockIdx.x;
    const int i = threadIdx.x;
    const unsigned mask = 0xffffu;
    __shared__ float sAt[16*16*16];
    __shared__ float sBC[64*32];

    for (int t = i; t < 4096/4; t += 16)
        reinterpret_cast<float4*>(sAt)[t] = reinterpret_cast<const float4*>(At)[t];

    const float* bcb = bc + (size_t)b*LSEQ*32;
    float*       hsb = hs + (size_t)b*LSEQ*DST;
    float h = 0.f;

    for (int l0 = 0; l0 < LSEQ; l0 += 64) {
        __syncwarp(mask);
        const float4* src = reinterpret_cast<const float4*>(bcb + (size_t)l0*32);
        for (int t = i; t < 64*32/4; t += 16)
            reinterpret_cast<float4*>(sBC)[t] = src[t];
        __syncwarp(mask);
        for (int ll = 0; ll < 64; ll++) {
            int l = l0 + ll;
            float Bv = sBC[ll*32 + i];
            float Cv = sBC[ll*32 + 16 + i];
            const float* Ar = &sAt[((l & 15) << 8) + (i << 4)];
            float a0 = Cv, a1 = 0.f, a2 = 0.f, a3 = Bv * h;
            #pragma unroll
            for (int j = 0; j < 16; j += 4) {
                a0 = fmaf(Ar[j+0], __shfl_sync(mask, h, j+0), a0);
                a1 = fmaf(Ar[j+1], __shfl_sync(mask, h, j+1), a1);
                a2 = fmaf(Ar[j+2], __shfl_sync(mask, h, j+2), a2);
                a3 = fmaf(Ar[j+3], __shfl_sync(mask, h, j+3), a3);
            }
            h = tanh_fast((a0 + a1) + (a2 + a3));
            hsb[(size_t)l*DST + i] = h;
        }
    }
}

// ---------------- rank-16 update: out += hs @ Wred^T (fp32) ------------------
__global__ void rank16_add(float* __restrict__ out,
                           const float* __restrict__ hs,
                           const float* __restrict__ Wred) {
    int m = blockIdx.x;
    int t = threadIdx.x;
    __shared__ float sh[16];
    if (t < 16) sh[t] = hs[(size_t)m * 16 + t];
    __syncthreads();
    float4 v = reinterpret_cast<float4*>(out)[(size_t)m * 256 + t];
    int n0 = t * 4;
    #pragma unroll
    for (int s = 0; s < 16; s++) {
        float hv = sh[s];
        v.x = fmaf(hv, Wred[(n0+0)*16 + s], v.x);
        v.y = fmaf(hv, Wred[(n0+1)*16 + s], v.y);
        v.z = fmaf(hv, Wred[(n0+2)*16 + s], v.z);
        v.w = fmaf(hv, Wred[(n0+3)*16 + s], v.w);
    }
    reinterpret_cast<float4*>(out)[(size_t)m * 256 + t] = v;
}

// ---------------- stream / event singletons ----------------------------------
static cudaStream_t side_stream() {
    static cudaStream_t s = []() {
        cudaStream_t t;
        cudaStreamCreateWithFlags(&t, cudaStreamNonBlocking);
        return t;
    }();
    return s;
}
static cudaEvent_t ev(int i) {
    static cudaEvent_t e[4] = {nullptr, nullptr, nullptr, nullptr};
    if (!e[0])
        for (int k = 0; k < 4; k++)
            cudaEventCreateWithFlags(&e[k], cudaEventDisableTiming);
    return e[i];
}

// ---------------- launcher ----------------------------------------------------
extern "C" void kernel_launch(void* const* d_in, const int* in_sizes, int n_in,
                              void* d_out, int out_size)
{
    const float* x      = (const float*)d_in[0];
    const float* W_in   = (const float*)d_in[1];
    const float* b_in   = (const float*)d_in[2];
    const float* conv_w = (const float*)d_in[3];
    const float* conv_b = (const float*)d_in[4];
    const float* W_x    = (const float*)d_in[5];
    const float* b_x    = (const float*)d_in[6];
    const float* dt     = (const float*)d_in[7];
    const float* A      = (const float*)d_in[8];
    const float* W_out  = (const float*)d_in[10];
    const float* b_out  = (const float*)d_in[11];
    float* out = (float*)d_out;

    float *bcv, *hsp, *Atp, *Wred, *bconst, *zerov;
    __nv_bfloat16 *xib, *xsb, *xh, *xl, *winh, *winTh, *winTl, *woh, *wol,
                  *wcombh, *wcombl, *wxh;
    cudaGetSymbolAddress((void**)&xib,    g_xib);
    cudaGetSymbolAddress((void**)&xsb,    g_xsb);
    cudaGetSymbolAddress((void**)&bcv,    g_bc);
    cudaGetSymbolAddress((void**)&hsp,    g_hs);
    cudaGetSymbolAddress((void**)&Atp,    g_At);
    cudaGetSymbolAddress((void**)&Wred,   g_Wred);
    cudaGetSymbolAddress((void**)&bconst, g_bconst);
    cudaGetSymbolAddress((void**)&zerov,  g_zero);
    cudaGetSymbolAddress((void**)&xh,     g_xh);
    cudaGetSymbolAddress((void**)&xl,     g_xl);
    cudaGetSymbolAddress((void**)&winh,   g_winh);
    cudaGetSymbolAddress((void**)&winTh,  g_winTh);
    cudaGetSymbolAddress((void**)&winTl,  g_winTl);
    cudaGetSymbolAddress((void**)&woh,    g_woh);
    cudaGetSymbolAddress((void**)&wol,    g_wol);
    cudaGetSymbolAddress((void**)&wcombh, g_wcombh);
    cudaGetSymbolAddress((void**)&wcombl, g_wcombl);
    cudaGetSymbolAddress((void**)&wxh,    g_wxh);

    // smem sizes
    const int SM_BIG1 = 3 * (16384 + 32768) + 1024;           // gemm_big P1 S3: 145K
    const int SM_BIG3 = 2 * (2*16384 + 2*32768) + 1024;       // gemm_big P3 S2: 193K
    const int SM_BC   = 3 * (16384 + 64*128) + 1024;          // gemm_mma P1 BN64
    const int SM_P364 = 3 * (2 * 16384 + 2 * 64*128) + 1024;  // gemm_mma P3 BN64
    cudaFuncSetAttribute(gemm_big<2,1,3>, cudaFuncAttributeMaxDynamicSharedMemorySize, SM_BIG1);
    cudaFuncSetAttribute(gemm_big<1,3,2>, cudaFuncAttributeMaxDynamicSharedMemorySize, SM_BIG3);
    cudaFuncSetAttribute(gemm_mma<3,1,64>, cudaFuncAttributeMaxDynamicSharedMemorySize, SM_BC);
    cudaFuncSetAttribute(gemm_mma<0,3,64>, cudaFuncAttributeMaxDynamicSharedMemorySize, SM_P364);

    cudaStream_t sd = side_stream();
    cudaEvent_t e_fork = ev(0), e_x = ev(1), e_hs = ev(2), e_done = ev(3);

    // ---- fork side stream at capture start ----
    cudaEventRecord(e_fork, 0);
    cudaStreamWaitEvent(sd, e_fork, 0);

    // ==== stream 0: xi chain (gemm1a kept at launch #4 for profiling) ====
    split_f32_v4<<<(int)(((long)MROWS*DMOD/4 + 255)/256), 256>>>(x, xh, xl, (long)MROWS*DMOD/4);
    cudaEventRecord(e_x, 0);
    split_hi_v4<<<(int)(((long)DINN*DMOD/4 + 255)/256), 256>>>(W_in, winh, (long)DINN*DMOD/4);
    prep_at<<<16, 256>>>(dt, A, Atp);
    gemm_big<2,1,3><<<dim3(DINN/256, MROWS/128), 256, SM_BIG1>>>(      // launch #4
        xh, nullptr, DMOD, winh, nullptr, DMOD, b_in,
        nullptr, 0, xib, DINN, DMOD);
    conv_silu<<<(MROWS*DINN)/256, 256>>>(xib, conv_w, conv_b, xsb);
    prep_wx<<<(128*DINN + 255)/256, 256>>>(W_x, wxh);
    gemm_mma<3,1,64><<<dim3(1, MROWS/128), 256, SM_BC>>>(
        xsb, nullptr, DINN, wxh, nullptr, DINN, b_x,
        bcv, 32, nullptr, nullptr, 0, DINN);
    scan_kernel<<<BATCH, 16>>>(bcv, Atp, hsp);
    cudaEventRecord(e_hs, 0);

    // ==== side stream: output chain ====
    split_f32_v4<<<(int)(((long)DMOD*DINN/4 + 255)/256), 256, 0, sd>>>(
        W_out, woh, wol, (long)DMOD*DINN/4);
    transpose_split<<<dim3(DINN/32, DMOD/32), dim3(32, 8), 0, sd>>>(
        W_in + (size_t)DINN*DMOD, winTh, winTl);
    prep_wred<<<64, 256, 0, sd>>>(W_out, Wred);
    prep_bconst<<<DMOD/8, 256, 0, sd>>>(W_out, b_in + DINN, b_out, bconst);

    // Wcomb = Wout @ Win2 (1024x1024, K=2048), 3-pass, split-bf16 out
    gemm_mma<0,3,64><<<dim3(DMOD/64, DMOD/128), 256, SM_P364, sd>>>(
        woh, wol, DINN, winTh, winTl, DINN, zerov,
        nullptr, 0, wcombh, wcombl, DMOD, DINN);
    // out = x @ Wcomb^T + bconst (3-pass big-tile)
    cudaStreamWaitEvent(sd, e_x, 0);
    gemm_big<1,3,2><<<dim3(DMOD/256, MROWS/128), 256, SM_BIG3, sd>>>(
        xh, xl, DMOD, wcombh, wcombl, DMOD, bconst,
        out, DMOD, nullptr, 0, DMOD);
    // out += hs @ Wred^T
    cudaStreamWaitEvent(sd, e_hs, 0);
    rank16_add<<<MROWS, 256, 0, sd>>>(out, hsp, Wred);
    cudaEventRecord(e_done, sd);

    // ---- join side stream before capture ends ----
    cudaStreamWaitEvent(0, e_done, 0);
}

// round 11
// speedup vs baseline: 1.2902x; 1.0329x over previous
#include <cuda_runtime.h>
#include <cuda_fp16.h>
#include <math.h>
#include <stdint.h>

#define BATCH 4
#define LSEQ  2048
#define DMOD  1024
#define DST   16
#define KCONV 4
#define DINN  2048
#define MROWS (BATCH*LSEQ)   /* 8192 */

// ---------------- scratch (device globals) -----------------------------------
__device__ __align__(128) __half g_xib[(size_t)MROWS * DINN];
__device__ __align__(128) __half g_xsb[(size_t)MROWS * DINN];
__device__ __align__(128) float g_bc[(size_t)MROWS * 32];
__device__ __align__(128) float g_hs[(size_t)MROWS * DST];
__device__ __align__(128) float g_At[16*16*16];
__device__ __align__(128) float g_Wred[DMOD*DST];
__device__ __align__(128) float g_bconst[DMOD];
__device__ __align__(128) float g_zero[DMOD];
__device__ __align__(128) __half g_xh[(size_t)MROWS*DMOD], g_xl[(size_t)MROWS*DMOD];
__device__ __align__(128) __half g_winh[(size_t)DINN*DMOD];
__device__ __align__(128) __half g_winTh[(size_t)DMOD*DINN];
__device__ __align__(128) __half g_woh[(size_t)DMOD*DINN], g_wol[(size_t)DMOD*DINN];
__device__ __align__(128) __half g_wcombh[(size_t)DMOD*DMOD];
__device__ __align__(128) __half g_wxh[(size_t)128*DINN];

// ============================ PTX helpers (arch-agnostic) ====================
__device__ __forceinline__ uint32_t smem_u32(const void* p) {
    uint32_t a;
    asm("{ .reg .u64 t; cvta.to.shared.u64 t, %1; cvt.u32.u64 %0, t; }"
        : "=r"(a) : "l"(p));
    return a;
}
__device__ __forceinline__ void cp16(uint32_t s, const void* g) {
    asm volatile("cp.async.cg.shared.global [%0], [%1], 16;" :: "r"(s), "l"(g));
}
#define CP_COMMIT() asm volatile("cp.async.commit_group;" ::: "memory")
template<int N> __device__ __forceinline__ void cp_wait() {
    asm volatile("cp.async.wait_group %0;" :: "n"(N) : "memory");
}
__device__ __forceinline__ void ldsm_x4(uint32_t& r0, uint32_t& r1,
                                        uint32_t& r2, uint32_t& r3, uint32_t a) {
    asm volatile("ldmatrix.sync.aligned.m8n8.x4.shared.b16 {%0,%1,%2,%3}, [%4];"
                 : "=r"(r0), "=r"(r1), "=r"(r2), "=r"(r3) : "r"(a));
}
__device__ __forceinline__ void mma16816(float* c,
    uint32_t a0, uint32_t a1, uint32_t a2, uint32_t a3, uint32_t b0, uint32_t b1) {
    asm volatile(
        "mma.sync.aligned.m16n8k16.row.col.f32.f16.f16.f32 "
        "{%0,%1,%2,%3}, {%4,%5,%6,%7}, {%8,%9}, {%0,%1,%2,%3};"
        : "+f"(c[0]), "+f"(c[1]), "+f"(c[2]), "+f"(c[3])
        : "r"(a0), "r"(a1), "r"(a2), "r"(a3), "r"(b0), "r"(b1));
}
__device__ __forceinline__ float tanh_fast(float x) {
    float r;
    asm("tanh.approx.f32 %0, %1;" : "=f"(r) : "f"(x));
    return r;
}
__device__ __forceinline__ uint32_t swz(uint32_t bo) { return bo ^ ((bo >> 3) & 0x70); }

// 256-thread tile loader (ROWS x 64 fp16 = ROWS x 128B, SW128 swizzled)
template<int ROWS>
__device__ __forceinline__ void load_tile_async(const __half* __restrict__ g,
                                                long row0, int ld, int k0,
                                                uint32_t sb, int tid) {
    #pragma unroll
    for (int t = 0; t < ROWS/32; t++) {
        int idx = tid + t * 256;
        int r = idx >> 3, cv = idx & 7;
        cp16(sb + swz((uint32_t)(r * 128 + cv * 16)),
             g + (row0 + r) * (long)ld + k0 + cv * 8);
    }
}

// ============== BIG-TILE GEMM: CTA 128x256, 8 warps 2x4, warp 64x64 ==========
// MODE 1: fp32 + bias out    MODE 2: fp16 + bias out
// PASSES 1: Ah*Bh            PASSES 2: Ah*Bh + Al*Bh (A split, B hi-only)
// 3-stage, single-sync pipeline (issue distance 2, 3rd buffer removes WAR sync)
template<int MODE, int PASSES>
__global__ __launch_bounds__(256, 1)
void gemm_big(const __half* __restrict__ Ah, const __half* __restrict__ Al, int lda,
              const __half* __restrict__ Bh, int ldb,
              const float* __restrict__ bias,
              float* __restrict__ Cout, int ldc,
              __half* __restrict__ outh, int ldr,
              int K)
{
    constexpr int ATILE = 16384;             // 128 x 128B
    constexpr int BTILE = 32768;             // 256 x 128B
    constexpr int OFF_AL = ATILE;
    constexpr int OFF_BH = (PASSES == 2) ? 2*ATILE : ATILE;
    constexpr int STAGE  = OFF_BH + BTILE;

    extern __shared__ char smem_raw[];
    uint32_t raw = smem_u32(smem_raw);
    const uint32_t sbase = (raw + 1023u) & ~1023u;

    const int tid  = threadIdx.x;
    const int wid  = tid >> 5, lane = tid & 31;
    const int warpM = wid & 1, warpN = wid >> 1;       // 2 x 4
    const long m0 = (long)blockIdx.y * 128;
    const int  n0 = blockIdx.x * 256;

    float acc[4][8][4];
    #pragma unroll
    for (int i = 0; i < 4; i++)
        #pragma unroll
        for (int j = 0; j < 8; j++)
            #pragma unroll
            for (int q = 0; q < 4; q++) acc[i][j][q] = 0.f;

    const int rowA0 = warpM * 64 + (lane & 7) + ((lane >> 3) & 1) * 8;   // + mi*16
    const int khA   = (lane >> 4) & 1;
    const int rowB0 = warpN * 64 + (lane & 7) + ((lane >> 4) & 1) * 8;   // + nb*16
    const int khB   = (lane >> 3) & 1;

    const int NC = K / 64;

    auto issue = [&](int c) {
        uint32_t st = sbase + (uint32_t)(c % 3) * STAGE;
        int k0 = c * 64;
        load_tile_async<128>(Ah, m0, lda, k0, st, tid);
        if (PASSES == 2) load_tile_async<128>(Al, m0, lda, k0, st + OFF_AL, tid);
        load_tile_async<256>(Bh, n0, ldb, k0, st + OFF_BH, tid);
        CP_COMMIT();
    };

    issue(0);
    if (NC > 1) issue(1);

    for (int c = 0; c < NC; c++) {
        if (c + 1 < NC) cp_wait<1>();
        else            cp_wait<0>();
        __syncthreads();
        if (c + 2 < NC) issue(c + 2);   // overwrites stage (c-1)%3: safe post-sync

        uint32_t st = sbase + (uint32_t)(c % 3) * STAGE;
        #pragma unroll
        for (int ks = 0; ks < 4; ks++) {
            uint32_t ah[4][4], al[4][4], bh[8][2];
            #pragma unroll
            for (int mi = 0; mi < 4; mi++) {
                uint32_t bo = swz((uint32_t)((rowA0 + mi*16) * 128 + ks*32 + khA*16));
                ldsm_x4(ah[mi][0], ah[mi][1], ah[mi][2], ah[mi][3], st + bo);
                if (PASSES == 2)
                    ldsm_x4(al[mi][0], al[mi][1], al[mi][2], al[mi][3], st + OFF_AL + bo);
            }
            #pragma unroll
            for (int nb = 0; nb < 4; nb++) {
                uint32_t bo = swz((uint32_t)((rowB0 + nb*16) * 128 + ks*32 + khB*16));
                ldsm_x4(bh[nb*2][0], bh[nb*2][1], bh[nb*2+1][0], bh[nb*2+1][1],
                        st + OFF_BH + bo);
            }
            #pragma unroll
            for (int mi = 0; mi < 4; mi++)
                #pragma unroll
                for (int nf = 0; nf < 8; nf++)
                    mma16816(acc[mi][nf], ah[mi][0], ah[mi][1], ah[mi][2], ah[mi][3],
                             bh[nf][0], bh[nf][1]);
            if (PASSES == 2) {
                #pragma unroll
                for (int mi = 0; mi < 4; mi++)
                    #pragma unroll
                    for (int nf = 0; nf < 8; nf++)
                        mma16816(acc[mi][nf], al[mi][0], al[mi][1], al[mi][2], al[mi][3],
                                 bh[nf][0], bh[nf][1]);
            }
        }
    }

    const int g  = lane >> 2, tg = lane & 3;
    #pragma unroll
    for (int mi = 0; mi < 4; mi++) {
        #pragma unroll
        for (int h = 0; h < 2; h++) {
            long m = m0 + warpM * 64 + mi * 16 + h * 8 + g;
            #pragma unroll
            for (int nf = 0; nf < 8; nf++) {
                int n = n0 + warpN * 64 + nf * 8 + tg * 2;
                float2 bv = *reinterpret_cast<const float2*>(&bias[n]);
                float v0 = acc[mi][nf][h*2+0] + bv.x;
                float v1 = acc[mi][nf][h*2+1] + bv.y;
                if (MODE == 2) {
                    __half2 p;
                    p.x = __float2half_rn(v0);
                    p.y = __float2half_rn(v1);
                    *reinterpret_cast<__half2*>(&outh[m * (long)ldr + n]) = p;
                } else {
                    *reinterpret_cast<float2*>(&Cout[m * (long)ldc + n]) =
                        make_float2(v0, v1);
                }
            }
        }
    }
}

// ============== small GEMM: CTA 128xBN, 8 warps 4x2 ==========================
// MODE 2: fp16-hi out + bias   MODE 3: fp32 + bias, n<32 only
// PASSES 1: Ah*Bh   PASSES 2: Ah*Bh + Al*Bh
template<int MODE, int PASSES, int BN_>
__global__ __launch_bounds__(256, 1)
void gemm_mma(const __half* __restrict__ Ah, const __half* __restrict__ Al, int lda,
              const __half* __restrict__ Bh, int ldb,
              const float* __restrict__ bias,
              float* __restrict__ Cout, int ldc,
              __half* __restrict__ outh, int ldr,
              int K)
{
    constexpr int ATILE = 16384;
    constexpr int BTILE = BN_ * 128;
    constexpr int OFF_AL = ATILE;
    constexpr int OFF_BH = (PASSES == 2) ? 2*ATILE : ATILE;
    constexpr int STAGE  = OFF_BH + BTILE;
    constexpr int NF = BN_ / 16;
    constexpr int NB = BN_ / 32;

    extern __shared__ char smem_raw[];
    uint32_t raw = smem_u32(smem_raw);
    const uint32_t sbase = (raw + 1023u) & ~1023u;

    const int tid  = threadIdx.x;
    const int wid  = tid >> 5, lane = tid & 31;
    const int warpM = wid & 3, warpN = wid >> 2;
    const long m0 = (long)blockIdx.y * 128;
    const int  n0 = blockIdx.x * BN_;

    float acc[2][NF][4];
    #pragma unroll
    for (int i = 0; i < 2; i++)
        #pragma unroll
        for (int j = 0; j < NF; j++)
            #pragma unroll
            for (int q = 0; q < 4; q++) acc[i][j][q] = 0.f;

    const int rowA0 = warpM * 32 + (lane & 7) + ((lane >> 3) & 1) * 8;
    const int khA   = (lane >> 4) & 1;
    const int rowB0 = warpN * (BN_/2) + (lane & 7) + ((lane >> 4) & 1) * 8;
    const int khB   = (lane >> 3) & 1;

    const int NC = K / 64;

    auto issue = [&](int c) {
        uint32_t st = sbase + (uint32_t)(c % 3) * STAGE;
        int k0 = c * 64;
        load_tile_async<128>(Ah, m0, lda, k0, st, tid);
        if (PASSES == 2) load_tile_async<128>(Al, m0, lda, k0, st + OFF_AL, tid);
        load_tile_async<BN_>(Bh, n0, ldb, k0, st + OFF_BH, tid);
        CP_COMMIT();
    };

    issue(0);
    if (NC > 1) issue(1);

    for (int c = 0; c < NC; c++) {
        if (c + 1 < NC) cp_wait<1>();
        else            cp_wait<0>();
        __syncthreads();
        if (c + 2 < NC) issue(c + 2);

        uint32_t st = sbase + (uint32_t)(c % 3) * STAGE;
        #pragma unroll
        for (int ks = 0; ks < 4; ks++) {
            uint32_t ah[2][4], al[2][4], bh[NF][2];
            #pragma unroll
            for (int mi = 0; mi < 2; mi++) {
                uint32_t bo = swz((uint32_t)((rowA0 + mi*16) * 128 + ks*32 + khA*16));
                ldsm_x4(ah[mi][0], ah[mi][1], ah[mi][2], ah[mi][3], st + bo);
                if (PASSES == 2)
                    ldsm_x4(al[mi][0], al[mi][1], al[mi][2], al[mi][3], st + OFF_AL + bo);
            }
            #pragma unroll
            for (int nb = 0; nb < NB; nb++) {
                uint32_t bo = swz((uint32_t)((rowB0 + nb*16) * 128 + ks*32 + khB*16));
                ldsm_x4(bh[nb*2][0], bh[nb*2][1], bh[nb*2+1][0], bh[nb*2+1][1],
                        st + OFF_BH + bo);
            }
            #pragma unroll
            for (int mi = 0; mi < 2; mi++)
                #pragma unroll
                for (int nf = 0; nf < NF; nf++)
                    mma16816(acc[mi][nf], ah[mi][0], ah[mi][1], ah[mi][2], ah[mi][3],
                             bh[nf][0], bh[nf][1]);
            if (PASSES == 2) {
                #pragma unroll
                for (int mi = 0; mi < 2; mi++)
                    #pragma unroll
                    for (int nf = 0; nf < NF; nf++)
                        mma16816(acc[mi][nf], al[mi][0], al[mi][1], al[mi][2], al[mi][3],
                                 bh[nf][0], bh[nf][1]);
            }
        }
    }

    const int g  = lane >> 2, tg = lane & 3;
    #pragma unroll
    for (int mi = 0; mi < 2; mi++) {
        #pragma unroll
        for (int h = 0; h < 2; h++) {
            long m = m0 + warpM * 32 + mi * 16 + h * 8 + g;
            #pragma unroll
            for (int nf = 0; nf < NF; nf++) {
                int n = n0 + warpN * (BN_/2) + nf * 8 + tg * 2;
                if (MODE == 3 && n >= 32) continue;
                float2 bv = *reinterpret_cast<const float2*>(&bias[n]);
                float v0 = acc[mi][nf][h*2+0] + bv.x;
                float v1 = acc[mi][nf][h*2+1] + bv.y;
                if (MODE == 2) {
                    __half2 p;
                    p.x = __float2half_rn(v0);
                    p.y = __float2half_rn(v1);
                    *reinterpret_cast<__half2*>(&outh[m * (long)ldr + n]) = p;
                } else {
                    *reinterpret_cast<float2*>(&Cout[m * (long)ldc + n]) =
                        make_float2(v0, v1);
                }
            }
        }
    }
}

// ---------------- prep kernels -----------------------------------------------
__global__ void prep_at(const float* __restrict__ dt, const float* __restrict__ A,
                        float* __restrict__ At) {
    int t = blockIdx.x * blockDim.x + threadIdx.x;
    if (t < 4096) {
        int j = t >> 8, e = t & 255;
        At[t] = expf(expf(dt[j]) * A[e]);
    }
}

__global__ void prep_wred(const float* __restrict__ Wout, float* __restrict__ Wred) {
    int t = blockIdx.x * blockDim.x + threadIdx.x;
    if (t < DMOD * DST) {
        int m = t >> 4, s = t & 15;
        float sum = 0.f;
        #pragma unroll 8
        for (int r = 0; r < DINN / DST; r++)
            sum += Wout[(size_t)m * DINN + r * DST + s];
        Wred[t] = sum;
    }
}

__global__ void split_f32_v4(const float* __restrict__ src,
                             __half* __restrict__ hi,
                             __half* __restrict__ lo, long n4) {
    long t = (long)blockIdx.x * blockDim.x + threadIdx.x;
    if (t < n4) {
        float4 v = reinterpret_cast<const float4*>(src)[t];
        __half h0 = __float2half_rn(v.x), h1 = __float2half_rn(v.y);
        __half h2 = __float2half_rn(v.z), h3 = __float2half_rn(v.w);
        __half2 ha; ha.x = h0; ha.y = h1;
        __half2 hb; hb.x = h2; hb.y = h3;
        __half2 la, lb;
        la.x = __float2half_rn(v.x - __half2float(h0));
        la.y = __float2half_rn(v.y - __half2float(h1));
        lb.x = __float2half_rn(v.z - __half2float(h2));
        lb.y = __float2half_rn(v.w - __half2float(h3));
        reinterpret_cast<__half2*>(hi)[t*2]   = ha;
        reinterpret_cast<__half2*>(hi)[t*2+1] = hb;
        reinterpret_cast<__half2*>(lo)[t*2]   = la;
        reinterpret_cast<__half2*>(lo)[t*2+1] = lb;
    }
}

__global__ void split_hi_v4(const float* __restrict__ src,
                            __half* __restrict__ hi, long n4) {
    long t = (long)blockIdx.x * blockDim.x + threadIdx.x;
    if (t < n4) {
        float4 v = reinterpret_cast<const float4*>(src)[t];
        __half2 ha; ha.x = __float2half_rn(v.x); ha.y = __float2half_rn(v.y);
        __half2 hb; hb.x = __float2half_rn(v.z); hb.y = __float2half_rn(v.w);
        reinterpret_cast<__half2*>(hi)[t*2]   = ha;
        reinterpret_cast<__half2*>(hi)[t*2+1] = hb;
    }
}

// transpose (hi only): src [DINN, DMOD] -> th [DMOD, DINN]
__global__ void transpose_hi(const float* __restrict__ src,
                             __half* __restrict__ th) {
    __shared__ float tile[32][33];
    int di0 = blockIdx.x * 32, dm0 = blockIdx.y * 32;
    int tx = threadIdx.x, ty = threadIdx.y;
    #pragma unroll
    for (int i = 0; i < 32; i += 8)
        tile[ty + i][tx] = src[(size_t)(di0 + ty + i) * DMOD + dm0 + tx];
    __syncthreads();
    #pragma unroll
    for (int i = 0; i < 32; i += 8) {
        size_t o = (size_t)(dm0 + ty + i) * DINN + di0 + tx;
        th[o] = __float2half_rn(tile[tx][ty + i]);
    }
}

__global__ void prep_bconst(const float* __restrict__ Wout,
                            const float* __restrict__ b2,
                            const float* __restrict__ bout,
                            float* __restrict__ bc) {
    int n = blockIdx.x * 8 + (threadIdx.x >> 5);
    int lane = threadIdx.x & 31;
    float s = 0.f;
    for (int k = lane; k < DINN; k += 32)
        s = fmaf(Wout[(size_t)n * DINN + k], b2[k], s);
    #pragma unroll
    for (int o = 16; o; o >>= 1) s += __shfl_xor_sync(0xffffffffu, s, o);
    if (lane == 0) bc[n] = s + bout[n];
}

__global__ void prep_wx(const float* __restrict__ Wx, __half* __restrict__ o) {
    int t = blockIdx.x * blockDim.x + threadIdx.x;
    if (t < 128 * DINN) {
        int n = t / DINN, k = t % DINN;
        o[t] = __float2half_rn((n < 32) ? Wx[(size_t)n * DINN + k] : 0.f);
    }
}

// ---------------- depthwise causal conv (K=4) + SiLU (scalar, coalesced) -----
__global__ void conv_silu(const __half* __restrict__ xi,
                          const float* __restrict__ w,
                          const float* __restrict__ cb,
                          __half* __restrict__ xs)
{
    long t = (long)blockIdx.x * blockDim.x + threadIdx.x;
    if (t >= (long)MROWS * DINN) return;
    int  c  = (int)(t & (DINN - 1));
    long bl = t >> 11;
    int  l  = (int)(bl & (LSEQ - 1));
    long row0 = bl - l;

    float4 wv = *reinterpret_cast<const float4*>(&w[c * 4]);
    float acc = cb[c];
    const float wk[4] = {wv.x, wv.y, wv.z, wv.w};
    #pragma unroll
    for (int k = 0; k < KCONV; k++) {
        int ll = l - (KCONV - 1) + k;
        if (ll >= 0)
            acc = fmaf(__half2float(xi[(size_t)(row0 + ll) * DINN + c]), wk[k], acc);
    }
    float s = 1.f / (1.f + expf(-acc));
    xs[t] = __float2half_rn(acc * s);
}

// ---------------- sequential nonlinear scan ----------------------------------
__global__ void scan_kernel(const float* __restrict__ bc,
                            const float* __restrict__ At,
                            float* __restrict__ hs)
{
    const int b = blockIdx.x;
    const int i = threadIdx.x;
    const unsigned mask = 0xffffu;
    __shared__ float sAt[16*16*16];
    __shared__ float sBC[64*32];

    for (int t = i; t < 4096/4; t += 16)
        reinterpret_cast<float4*>(sAt)[t] = reinterpret_cast<const float4*>(At)[t];

    const float* bcb = bc + (size_t)b*LSEQ*32;
    float*       hsb = hs + (size_t)b*LSEQ*DST;
    float h = 0.f;

    for (int l0 = 0; l0 < LSEQ; l0 += 64) {
        __syncwarp(mask);
        const float4* src = reinterpret_cast<const float4*>(bcb + (size_t)l0*32);
        for (int t = i; t < 64*32/4; t += 16)
            reinterpret_cast<float4*>(sBC)[t] = src[t];
        __syncwarp(mask);
        for (int ll = 0; ll < 64; ll++) {
            int l = l0 + ll;
            float Bv = sBC[ll*32 + i];
            float Cv = sBC[ll*32 + 16 + i];
            const float* Ar = &sAt[((l & 15) << 8) + (i << 4)];
            float a0 = Cv, a1 = 0.f, a2 = 0.f, a3 = Bv * h;
            #pragma unroll
            for (int j = 0; j < 16; j += 4) {
                a0 = fmaf(Ar[j+0], __shfl_sync(mask, h, j+0), a0);
                a1 = fmaf(Ar[j+1], __shfl_sync(mask, h, j+1), a1);
                a2 = fmaf(Ar[j+2], __shfl_sync(mask, h, j+2), a2);
                a3 = fmaf(Ar[j+3], __shfl_sync(mask, h, j+3), a3);
            }
            h = tanh_fast((a0 + a1) + (a2 + a3));
            hsb[(size_t)l*DST + i] = h;
        }
    }
}

// ---------------- rank-16 update: out += hs @ Wred^T (fp32) ------------------
__global__ void rank16_add(float* __restrict__ out,
                           const float* __restrict__ hs,
                           const float* __restrict__ Wred) {
    int m = blockIdx.x;
    int t = threadIdx.x;
    __shared__ float sh[16];
    if (t < 16) sh[t] = hs[(size_t)m * 16 + t];
    __syncthreads();
    float4 v = reinterpret_cast<float4*>(out)[(size_t)m * 256 + t];
    int n0 = t * 4;
    #pragma unroll
    for (int s = 0; s < 16; s++) {
        float hv = sh[s];
        v.x = fmaf(hv, Wred[(n0+0)*16 + s], v.x);
        v.y = fmaf(hv, Wred[(n0+1)*16 + s], v.y);
        v.z = fmaf(hv, Wred[(n0+2)*16 + s], v.z);
        v.w = fmaf(hv, Wred[(n0+3)*16 + s], v.w);
    }
    reinterpret_cast<float4*>(out)[(size_t)m * 256 + t] = v;
}

// ---------------- stream / event singletons ----------------------------------
static cudaStream_t side_stream() {
    static cudaStream_t s = []() {
        cudaStream_t t;
        cudaStreamCreateWithFlags(&t, cudaStreamNonBlocking);
        return t;
    }();
    return s;
}
static cudaEvent_t ev(int i) {
    static cudaEvent_t e[4] = {nullptr, nullptr, nullptr, nullptr};
    if (!e[0])
        for (int k = 0; k < 4; k++)
            cudaEventCreateWithFlags(&e[k], cudaEventDisableTiming);
    return e[i];
}

// ---------------- launcher ----------------------------------------------------
extern "C" void kernel_launch(void* const* d_in, const int* in_sizes, int n_in,
                              void* d_out, int out_size)
{
    const float* x      = (const float*)d_in[0];
    const float* W_in   = (const float*)d_in[1];
    const float* b_in   = (const float*)d_in[2];
    const float* conv_w = (const float*)d_in[3];
    const float* conv_b = (const float*)d_in[4];
    const float* W_x    = (const float*)d_in[5];
    const float* b_x    = (const float*)d_in[6];
    const float* dt     = (const float*)d_in[7];
    const float* A      = (const float*)d_in[8];
    const float* W_out  = (const float*)d_in[10];
    const float* b_out  = (const float*)d_in[11];
    float* out = (float*)d_out;

    float *bcv, *hsp, *Atp, *Wred, *bconst, *zerov;
    __half *xib, *xsb, *xh, *xl, *winh, *winTh, *woh, *wol, *wcombh, *wxh;
    cudaGetSymbolAddress((void**)&xib,    g_xib);
    cudaGetSymbolAddress((void**)&xsb,    g_xsb);
    cudaGetSymbolAddress((void**)&bcv,    g_bc);
    cudaGetSymbolAddress((void**)&hsp,    g_hs);
    cudaGetSymbolAddress((void**)&Atp,    g_At);
    cudaGetSymbolAddress((void**)&Wred,   g_Wred);
    cudaGetSymbolAddress((void**)&bconst, g_bconst);
    cudaGetSymbolAddress((void**)&zerov,  g_zero);
    cudaGetSymbolAddress((void**)&xh,     g_xh);
    cudaGetSymbolAddress((void**)&xl,     g_xl);
    cudaGetSymbolAddress((void**)&winh,   g_winh);
    cudaGetSymbolAddress((void**)&winTh,  g_winTh);
    cudaGetSymbolAddress((void**)&woh,    g_woh);
    cudaGetSymbolAddress((void**)&wol,    g_wol);
    cudaGetSymbolAddress((void**)&wcombh, g_wcombh);
    cudaGetSymbolAddress((void**)&wxh,    g_wxh);

    // smem sizes
    const int SM_BIG1 = 3 * (16384 + 32768) + 1024;            // big P1: 145K
    const int SM_BIG2 = 3 * (2*16384 + 32768) + 1024;          // big P2: 193K
    const int SM_BC   = 3 * (16384 + 64*128) + 1024;           // small P1 BN64
    const int SM_WC   = 3 * (2*16384 + 64*128) + 1024;         // small P2 BN64
    cudaFuncSetAttribute(gemm_big<2,1>, cudaFuncAttributeMaxDynamicSharedMemorySize, SM_BIG1);
    cudaFuncSetAttribute(gemm_big<1,2>, cudaFuncAttributeMaxDynamicSharedMemorySize, SM_BIG2);
    cudaFuncSetAttribute(gemm_mma<3,1,64>, cudaFuncAttributeMaxDynamicSharedMemorySize, SM_BC);
    cudaFuncSetAttribute(gemm_mma<2,2,64>, cudaFuncAttributeMaxDynamicSharedMemorySize, SM_WC);

    cudaStream_t sd = side_stream();
    cudaEvent_t e_fork = ev(0), e_x = ev(1), e_hs = ev(2), e_done = ev(3);

    // ---- fork side stream at capture start ----
    cudaEventRecord(e_fork, 0);
    cudaStreamWaitEvent(sd, e_fork, 0);

    // ==== stream 0: xi chain (gemm1a kept at launch #4 for profiling) ====
    split_f32_v4<<<(int)(((long)MROWS*DMOD/4 + 255)/256), 256>>>(x, xh, xl, (long)MROWS*DMOD/4);
    cudaEventRecord(e_x, 0);
    split_hi_v4<<<(int)(((long)DINN*DMOD/4 + 255)/256), 256>>>(W_in, winh, (long)DINN*DMOD/4);
    prep_at<<<16, 256>>>(dt, A, Atp);
    gemm_big<2,1><<<dim3(DINN/256, MROWS/128), 256, SM_BIG1>>>(        // launch #4
        xh, nullptr, DMOD, winh, DMOD, b_in,
        nullptr, 0, xib, DINN, DMOD);
    conv_silu<<<(MROWS*DINN)/256, 256>>>(xib, conv_w, conv_b, xsb);
    prep_wx<<<(128*DINN + 255)/256, 256>>>(W_x, wxh);
    gemm_mma<3,1,64><<<dim3(1, MROWS/128), 256, SM_BC>>>(
        xsb, nullptr, DINN, wxh, DINN, b_x,
        bcv, 32, nullptr, 0, DINN);
    scan_kernel<<<BATCH, 16>>>(bcv, Atp, hsp);
    cudaEventRecord(e_hs, 0);

    // ==== side stream: output chain ====
    split_f32_v4<<<(int)(((long)DMOD*DINN/4 + 255)/256), 256, 0, sd>>>(
        W_out, woh, wol, (long)DMOD*DINN/4);
    transpose_hi<<<dim3(DINN/32, DMOD/32), dim3(32, 8), 0, sd>>>(
        W_in + (size_t)DINN*DMOD, winTh);
    prep_wred<<<64, 256, 0, sd>>>(W_out, Wred);
    prep_bconst<<<DMOD/8, 256, 0, sd>>>(W_out, b_in + DINN, b_out, bconst);

    // Wcomb = Wout @ Win2 (1024x1024, K=2048), 2-pass, fp16-hi out
    gemm_mma<2,2,64><<<dim3(DMOD/64, DMOD/128), 256, SM_WC, sd>>>(
        woh, wol, DINN, winTh, DINN, zerov,
        nullptr, 0, wcombh, DMOD, DINN);
    // out = x @ Wcomb^T + bconst (2-pass big-tile: x split, Wcomb hi)
    cudaStreamWaitEvent(sd, e_x, 0);
    gemm_big<1,2><<<dim3(DMOD/256, MROWS/128), 256, SM_BIG2, sd>>>(
        xh, xl, DMOD, wcombh, DMOD, bconst,
        out, DMOD, nullptr, 0, DMOD);
    // out += hs @ Wred^T
    cudaStreamWaitEvent(sd, e_hs, 0);
    rank16_add<<<MROWS, 256, 0, sd>>>(out, hsp, Wred);
    cudaEventRecord(e_done, sd);

    // ---- join side stream before capture ends ----
    cudaStreamWaitEvent(0, e_done, 0);
}

// round 12
// speedup vs baseline: 1.3436x; 1.0414x over previous
#include <cuda_runtime.h>
#include <cuda_fp16.h>
#include <math.h>
#include <stdint.h>

#define BATCH 4
#define LSEQ  2048
#define DMOD  1024
#define DST   16
#define KCONV 4
#define DINN  2048
#define MROWS (BATCH*LSEQ)   /* 8192 */

// ---------------- scratch (device globals) -----------------------------------
__device__ __align__(128) __half g_xib[(size_t)MROWS * DINN];
__device__ __align__(128) __half g_xsb[(size_t)MROWS * DINN];
__device__ __align__(128) float g_bc[(size_t)MROWS * 32];
__device__ __align__(128) float g_hs[(size_t)MROWS * DST];
__device__ __align__(128) float g_At[16*16*16];
__device__ __align__(128) float g_Wred[DMOD*DST];
__device__ __align__(128) float g_bconst[DMOD];
__device__ __align__(128) float g_zero[DMOD];
__device__ __align__(128) __half g_xh[(size_t)MROWS*DMOD], g_xl[(size_t)MROWS*DMOD];
__device__ __align__(128) __half g_winh[(size_t)DINN*DMOD];
__device__ __align__(128) __half g_winTh[(size_t)DMOD*DINN];
__device__ __align__(128) __half g_woh[(size_t)DMOD*DINN], g_wol[(size_t)DMOD*DINN];
__device__ __align__(128) __half g_wcombh[(size_t)DMOD*DMOD];
__device__ __align__(128) __half g_wxh[(size_t)128*DINN];

// ============================ PTX helpers (arch-agnostic) ====================
__device__ __forceinline__ uint32_t smem_u32(const void* p) {
    uint32_t a;
    asm("{ .reg .u64 t; cvta.to.shared.u64 t, %1; cvt.u32.u64 %0, t; }"
        : "=r"(a) : "l"(p));
    return a;
}
__device__ __forceinline__ void cp16(uint32_t s, const void* g) {
    asm volatile("cp.async.cg.shared.global [%0], [%1], 16;" :: "r"(s), "l"(g));
}
#define CP_COMMIT() asm volatile("cp.async.commit_group;" ::: "memory")
template<int N> __device__ __forceinline__ void cp_wait() {
    asm volatile("cp.async.wait_group %0;" :: "n"(N) : "memory");
}
__device__ __forceinline__ void ldsm_x4(uint32_t& r0, uint32_t& r1,
                                        uint32_t& r2, uint32_t& r3, uint32_t a) {
    asm volatile("ldmatrix.sync.aligned.m8n8.x4.shared.b16 {%0,%1,%2,%3}, [%4];"
                 : "=r"(r0), "=r"(r1), "=r"(r2), "=r"(r3) : "r"(a));
}
__device__ __forceinline__ void mma16816(float* c,
    uint32_t a0, uint32_t a1, uint32_t a2, uint32_t a3, uint32_t b0, uint32_t b1) {
    asm volatile(
        "mma.sync.aligned.m16n8k16.row.col.f32.f16.f16.f32 "
        "{%0,%1,%2,%3}, {%4,%5,%6,%7}, {%8,%9}, {%0,%1,%2,%3};"
        : "+f"(c[0]), "+f"(c[1]), "+f"(c[2]), "+f"(c[3])
        : "r"(a0), "r"(a1), "r"(a2), "r"(a3), "r"(b0), "r"(b1));
}
__device__ __forceinline__ float tanh_fast(float x) {
    float r;
    asm("tanh.approx.f32 %0, %1;" : "=f"(r) : "f"(x));
    return r;
}
__device__ __forceinline__ uint32_t swz(uint32_t bo) { return bo ^ ((bo >> 3) & 0x70); }

// 256-thread tile loader (ROWS x 64 fp16 = ROWS x 128B, SW128 swizzled)
template<int ROWS>
__device__ __forceinline__ void load_tile_async(const __half* __restrict__ g,
                                                long row0, int ld, int k0,
                                                uint32_t sb, int tid) {
    #pragma unroll
    for (int t = 0; t < ROWS/32; t++) {
        int idx = tid + t * 256;
        int r = idx >> 3, cv = idx & 7;
        cp16(sb + swz((uint32_t)(r * 128 + cv * 16)),
             g + (row0 + r) * (long)ld + k0 + cv * 8);
    }
}

// ============== BIG-TILE GEMM: CTA 128x256, 8 warps 2x4, warp 64x64 ==========
// MODE 1: fp32 + bias out    MODE 2: fp16 + bias out
// PASSES 1: Ah*Bh            PASSES 2: Ah*Bh + Al*Bh (A split, B hi-only)
template<int MODE, int PASSES>
__global__ __launch_bounds__(256, 1)
void gemm_big(const __half* __restrict__ Ah, const __half* __restrict__ Al, int lda,
              const __half* __restrict__ Bh, int ldb,
              const float* __restrict__ bias,
              float* __restrict__ Cout, int ldc,
              __half* __restrict__ outh, int ldr,
              int K)
{
    constexpr int ATILE = 16384;             // 128 x 128B
    constexpr int BTILE = 32768;             // 256 x 128B
    constexpr int OFF_AL = ATILE;
    constexpr int OFF_BH = (PASSES == 2) ? 2*ATILE : ATILE;
    constexpr int STAGE  = OFF_BH + BTILE;

    extern __shared__ char smem_raw[];
    uint32_t raw = smem_u32(smem_raw);
    const uint32_t sbase = (raw + 1023u) & ~1023u;

    const int tid  = threadIdx.x;
    const int wid  = tid >> 5, lane = tid & 31;
    const int warpM = wid & 1, warpN = wid >> 1;       // 2 x 4
    const long m0 = (long)blockIdx.y * 128;
    const int  n0 = blockIdx.x * 256;

    float acc[4][8][4];
    #pragma unroll
    for (int i = 0; i < 4; i++)
        #pragma unroll
        for (int j = 0; j < 8; j++)
            #pragma unroll
            for (int q = 0; q < 4; q++) acc[i][j][q] = 0.f;

    const int rowA0 = warpM * 64 + (lane & 7) + ((lane >> 3) & 1) * 8;
    const int khA   = (lane >> 4) & 1;
    const int rowB0 = warpN * 64 + (lane & 7) + ((lane >> 4) & 1) * 8;
    const int khB   = (lane >> 3) & 1;

    const int NC = K / 64;

    auto issue = [&](int c) {
        uint32_t st = sbase + (uint32_t)(c % 3) * STAGE;
        int k0 = c * 64;
        load_tile_async<128>(Ah, m0, lda, k0, st, tid);
        if (PASSES == 2) load_tile_async<128>(Al, m0, lda, k0, st + OFF_AL, tid);
        load_tile_async<256>(Bh, n0, ldb, k0, st + OFF_BH, tid);
        CP_COMMIT();
    };

    issue(0);
    if (NC > 1) issue(1);

    for (int c = 0; c < NC; c++) {
        if (c + 1 < NC) cp_wait<1>();
        else            cp_wait<0>();
        __syncthreads();
        if (c + 2 < NC) issue(c + 2);

        uint32_t st = sbase + (uint32_t)(c % 3) * STAGE;
        #pragma unroll
        for (int ks = 0; ks < 4; ks++) {
            uint32_t ah[4][4], al[4][4], bh[8][2];
            #pragma unroll
            for (int mi = 0; mi < 4; mi++) {
                uint32_t bo = swz((uint32_t)((rowA0 + mi*16) * 128 + ks*32 + khA*16));
                ldsm_x4(ah[mi][0], ah[mi][1], ah[mi][2], ah[mi][3], st + bo);
                if (PASSES == 2)
                    ldsm_x4(al[mi][0], al[mi][1], al[mi][2], al[mi][3], st + OFF_AL + bo);
            }
            #pragma unroll
            for (int nb = 0; nb < 4; nb++) {
                uint32_t bo = swz((uint32_t)((rowB0 + nb*16) * 128 + ks*32 + khB*16));
                ldsm_x4(bh[nb*2][0], bh[nb*2][1], bh[nb*2+1][0], bh[nb*2+1][1],
                        st + OFF_BH + bo);
            }
            #pragma unroll
            for (int mi = 0; mi < 4; mi++)
                #pragma unroll
                for (int nf = 0; nf < 8; nf++)
                    mma16816(acc[mi][nf], ah[mi][0], ah[mi][1], ah[mi][2], ah[mi][3],
                             bh[nf][0], bh[nf][1]);
            if (PASSES == 2) {
                #pragma unroll
                for (int mi = 0; mi < 4; mi++)
                    #pragma unroll
                    for (int nf = 0; nf < 8; nf++)
                        mma16816(acc[mi][nf], al[mi][0], al[mi][1], al[mi][2], al[mi][3],
                                 bh[nf][0], bh[nf][1]);
            }
        }
    }

    const int g  = lane >> 2, tg = lane & 3;
    #pragma unroll
    for (int mi = 0; mi < 4; mi++) {
        #pragma unroll
        for (int h = 0; h < 2; h++) {
            long m = m0 + warpM * 64 + mi * 16 + h * 8 + g;
            #pragma unroll
            for (int nf = 0; nf < 8; nf++) {
                int n = n0 + warpN * 64 + nf * 8 + tg * 2;
                float2 bv = *reinterpret_cast<const float2*>(&bias[n]);
                float v0 = acc[mi][nf][h*2+0] + bv.x;
                float v1 = acc[mi][nf][h*2+1] + bv.y;
                if (MODE == 2) {
                    __half2 p;
                    p.x = __float2half_rn(v0);
                    p.y = __float2half_rn(v1);
                    *reinterpret_cast<__half2*>(&outh[m * (long)ldr + n]) = p;
                } else {
                    *reinterpret_cast<float2*>(&Cout[m * (long)ldc + n]) =
                        make_float2(v0, v1);
                }
            }
        }
    }
}

// ============== small GEMM: CTA 128xBN, 8 warps 4x2 ==========================
// MODE 2: fp16-hi out + bias            MODE 3: fp32 + bias, n<32 only
// MODE 4: split-K: blockIdx.x = K-slice, atomicAdd fp32, bias on slice 0, n<32
// PASSES 1: Ah*Bh   PASSES 2: Ah*Bh + Al*Bh
template<int MODE, int PASSES, int BN_>
__global__ __launch_bounds__(256, 1)
void gemm_mma(const __half* __restrict__ Ah, const __half* __restrict__ Al, int lda,
              const __half* __restrict__ Bh, int ldb,
              const float* __restrict__ bias,
              float* __restrict__ Cout, int ldc,
              __half* __restrict__ outh, int ldr,
              int K)
{
    constexpr int ATILE = 16384;
    constexpr int BTILE = BN_ * 128;
    constexpr int OFF_AL = ATILE;
    constexpr int OFF_BH = (PASSES == 2) ? 2*ATILE : ATILE;
    constexpr int STAGE  = OFF_BH + BTILE;
    constexpr int NF = BN_ / 16;
    constexpr int NB = BN_ / 32;

    extern __shared__ char smem_raw[];
    uint32_t raw = smem_u32(smem_raw);
    const uint32_t sbase = (raw + 1023u) & ~1023u;

    const int tid  = threadIdx.x;
    const int wid  = tid >> 5, lane = tid & 31;
    const int warpM = wid & 3, warpN = wid >> 2;
    const long m0 = (long)blockIdx.y * 128;
    const int  n0 = (MODE == 4) ? 0 : blockIdx.x * BN_;
    const int  koff = (MODE == 4) ? blockIdx.x * K : 0;

    float acc[2][NF][4];
    #pragma unroll
    for (int i = 0; i < 2; i++)
        #pragma unroll
        for (int j = 0; j < NF; j++)
            #pragma unroll
            for (int q = 0; q < 4; q++) acc[i][j][q] = 0.f;

    const int rowA0 = warpM * 32 + (lane & 7) + ((lane >> 3) & 1) * 8;
    const int khA   = (lane >> 4) & 1;
    const int rowB0 = warpN * (BN_/2) + (lane & 7) + ((lane >> 4) & 1) * 8;
    const int khB   = (lane >> 3) & 1;

    const int NC = K / 64;

    auto issue = [&](int c) {
        uint32_t st = sbase + (uint32_t)(c % 3) * STAGE;
        int k0 = c * 64 + koff;
        load_tile_async<128>(Ah, m0, lda, k0, st, tid);
        if (PASSES == 2) load_tile_async<128>(Al, m0, lda, k0, st + OFF_AL, tid);
        load_tile_async<BN_>(Bh, n0, ldb, k0, st + OFF_BH, tid);
        CP_COMMIT();
    };

    issue(0);
    if (NC > 1) issue(1);

    for (int c = 0; c < NC; c++) {
        if (c + 1 < NC) cp_wait<1>();
        else            cp_wait<0>();
        __syncthreads();
        if (c + 2 < NC) issue(c + 2);

        uint32_t st = sbase + (uint32_t)(c % 3) * STAGE;
        #pragma unroll
        for (int ks = 0; ks < 4; ks++) {
            uint32_t ah[2][4], al[2][4], bh[NF][2];
            #pragma unroll
            for (int mi = 0; mi < 2; mi++) {
                uint32_t bo = swz((uint32_t)((rowA0 + mi*16) * 128 + ks*32 + khA*16));
                ldsm_x4(ah[mi][0], ah[mi][1], ah[mi][2], ah[mi][3], st + bo);
                if (PASSES == 2)
                    ldsm_x4(al[mi][0], al[mi][1], al[mi][2], al[mi][3], st + OFF_AL + bo);
            }
            #pragma unroll
            for (int nb = 0; nb < NB; nb++) {
                uint32_t bo = swz((uint32_t)((rowB0 + nb*16) * 128 + ks*32 + khB*16));
                ldsm_x4(bh[nb*2][0], bh[nb*2][1], bh[nb*2+1][0], bh[nb*2+1][1],
                        st + OFF_BH + bo);
            }
            #pragma unroll
            for (int mi = 0; mi < 2; mi++)
                #pragma unroll
                for (int nf = 0; nf < NF; nf++)
                    mma16816(acc[mi][nf], ah[mi][0], ah[mi][1], ah[mi][2], ah[mi][3],
                             bh[nf][0], bh[nf][1]);
            if (PASSES == 2) {
                #pragma unroll
                for (int mi = 0; mi < 2; mi++)
                    #pragma unroll
                    for (int nf = 0; nf < NF; nf++)
                        mma16816(acc[mi][nf], al[mi][0], al[mi][1], al[mi][2], al[mi][3],
                                 bh[nf][0], bh[nf][1]);
            }
        }
    }

    const int g  = lane >> 2, tg = lane & 3;
    #pragma unroll
    for (int mi = 0; mi < 2; mi++) {
        #pragma unroll
        for (int h = 0; h < 2; h++) {
            long m = m0 + warpM * 32 + mi * 16 + h * 8 + g;
            #pragma unroll
            for (int nf = 0; nf < NF; nf++) {
                int n = n0 + warpN * (BN_/2) + nf * 8 + tg * 2;
                if ((MODE == 3 || MODE == 4) && n >= 32) continue;
                float b0 = 0.f, b1 = 0.f;
                if (MODE != 4 || blockIdx.x == 0) {
                    float2 bv = *reinterpret_cast<const float2*>(&bias[n]);
                    b0 = bv.x; b1 = bv.y;
                }
                float v0 = acc[mi][nf][h*2+0] + b0;
                float v1 = acc[mi][nf][h*2+1] + b1;
                if (MODE == 4) {
                    atomicAdd(&Cout[m * (long)ldc + n],     v0);
                    atomicAdd(&Cout[m * (long)ldc + n + 1], v1);
                } else if (MODE == 2) {
                    __half2 p;
                    p.x = __float2half_rn(v0);
                    p.y = __float2half_rn(v1);
                    *reinterpret_cast<__half2*>(&outh[m * (long)ldr + n]) = p;
                } else {
                    *reinterpret_cast<float2*>(&Cout[m * (long)ldc + n]) =
                        make_float2(v0, v1);
                }
            }
        }
    }
}

// ---------------- prep kernels -----------------------------------------------
__global__ void prep_at(const float* __restrict__ dt, const float* __restrict__ A,
                        float* __restrict__ At) {
    int t = blockIdx.x * blockDim.x + threadIdx.x;
    if (t < 4096) {
        int j = t >> 8, e = t & 255;
        At[t] = expf(expf(dt[j]) * A[e]);
    }
}

__global__ void prep_wred(const float* __restrict__ Wout, float* __restrict__ Wred) {
    int t = blockIdx.x * blockDim.x + threadIdx.x;
    if (t < DMOD * DST) {
        int m = t >> 4, s = t & 15;
        float sum = 0.f;
        #pragma unroll 8
        for (int r = 0; r < DINN / DST; r++)
            sum += Wout[(size_t)m * DINN + r * DST + s];
        Wred[t] = sum;
    }
}

__global__ void split_f32_v4(const float* __restrict__ src,
                             __half* __restrict__ hi,
                             __half* __restrict__ lo, long n4) {
    long t = (long)blockIdx.x * blockDim.x + threadIdx.x;
    if (t < n4) {
        float4 v = reinterpret_cast<const float4*>(src)[t];
        __half h0 = __float2half_rn(v.x), h1 = __float2half_rn(v.y);
        __half h2 = __float2half_rn(v.z), h3 = __float2half_rn(v.w);
        __half2 ha; ha.x = h0; ha.y = h1;
        __half2 hb; hb.x = h2; hb.y = h3;
        __half2 la, lb;
        la.x = __float2half_rn(v.x - __half2float(h0));
        la.y = __float2half_rn(v.y - __half2float(h1));
        lb.x = __float2half_rn(v.z - __half2float(h2));
        lb.y = __float2half_rn(v.w - __half2float(h3));
        reinterpret_cast<__half2*>(hi)[t*2]   = ha;
        reinterpret_cast<__half2*>(hi)[t*2+1] = hb;
        reinterpret_cast<__half2*>(lo)[t*2]   = la;
        reinterpret_cast<__half2*>(lo)[t*2+1] = lb;
    }
}

__global__ void split_hi_v4(const float* __restrict__ src,
                            __half* __restrict__ hi, long n4) {
    long t = (long)blockIdx.x * blockDim.x + threadIdx.x;
    if (t < n4) {
        float4 v = reinterpret_cast<const float4*>(src)[t];
        __half2 ha; ha.x = __float2half_rn(v.x); ha.y = __float2half_rn(v.y);
        __half2 hb; hb.x = __float2half_rn(v.z); hb.y = __float2half_rn(v.w);
        reinterpret_cast<__half2*>(hi)[t*2]   = ha;
        reinterpret_cast<__half2*>(hi)[t*2+1] = hb;
    }
}

// transpose (hi only): src [DINN, DMOD] -> th [DMOD, DINN]
__global__ void transpose_hi(const float* __restrict__ src,
                             __half* __restrict__ th) {
    __shared__ float tile[32][33];
    int di0 = blockIdx.x * 32, dm0 = blockIdx.y * 32;
    int tx = threadIdx.x, ty = threadIdx.y;
    #pragma unroll
    for (int i = 0; i < 32; i += 8)
        tile[ty + i][tx] = src[(size_t)(di0 + ty + i) * DMOD + dm0 + tx];
    __syncthreads();
    #pragma unroll
    for (int i = 0; i < 32; i += 8) {
        size_t o = (size_t)(dm0 + ty + i) * DINN + di0 + tx;
        th[o] = __float2half_rn(tile[tx][ty + i]);
    }
}

__global__ void prep_bconst(const float* __restrict__ Wout,
                            const float* __restrict__ b2,
                            const float* __restrict__ bout,
                            float* __restrict__ bc) {
    int n = blockIdx.x * 8 + (threadIdx.x >> 5);
    int lane = threadIdx.x & 31;
    float s = 0.f;
    for (int k = lane; k < DINN; k += 32)
        s = fmaf(Wout[(size_t)n * DINN + k], b2[k], s);
    #pragma unroll
    for (int o = 16; o; o >>= 1) s += __shfl_xor_sync(0xffffffffu, s, o);
    if (lane == 0) bc[n] = s + bout[n];
}

__global__ void prep_wx(const float* __restrict__ Wx, __half* __restrict__ o) {
    int t = blockIdx.x * blockDim.x + threadIdx.x;
    if (t < 128 * DINN) {
        int n = t / DINN, k = t % DINN;
        o[t] = __float2half_rn((n < 32) ? Wx[(size_t)n * DINN + k] : 0.f);
    }
}

// ---------------- depthwise causal conv (K=4) + SiLU (scalar, coalesced) -----
__global__ void conv_silu(const __half* __restrict__ xi,
                          const float* __restrict__ w,
                          const float* __restrict__ cb,
                          __half* __restrict__ xs)
{
    long t = (long)blockIdx.x * blockDim.x + threadIdx.x;
    if (t >= (long)MROWS * DINN) return;
    int  c  = (int)(t & (DINN - 1));
    long bl = t >> 11;
    int  l  = (int)(bl & (LSEQ - 1));
    long row0 = bl - l;

    float4 wv = *reinterpret_cast<const float4*>(&w[c * 4]);
    float acc = cb[c];
    const float wk[4] = {wv.x, wv.y, wv.z, wv.w};
    #pragma unroll
    for (int k = 0; k < KCONV; k++) {
        int ll = l - (KCONV - 1) + k;
        if (ll >= 0)
            acc = fmaf(__half2float(xi[(size_t)(row0 + ll) * DINN + c]), wk[k], acc);
    }
    float s = 1.f / (1.f + expf(-acc));
    xs[t] = __float2half_rn(acc * s);
}

// ---------------- sequential nonlinear scan ----------------------------------
__global__ void scan_kernel(const float* __restrict__ bc,
                            const float* __restrict__ At,
                            float* __restrict__ hs)
{
    const int b = blockIdx.x;
    const int i = threadIdx.x;
    const unsigned mask = 0xffffu;
    __shared__ float sAt[16*16*16];
    __shared__ float sBC[64*32];

    for (int t = i; t < 4096/4; t += 16)
        reinterpret_cast<float4*>(sAt)[t] = reinterpret_cast<const float4*>(At)[t];

    const float* bcb = bc + (size_t)b*LSEQ*32;
    float*       hsb = hs + (size_t)b*LSEQ*DST;
    float h = 0.f;

    for (int l0 = 0; l0 < LSEQ; l0 += 64) {
        __syncwarp(mask);
        const float4* src = reinterpret_cast<const float4*>(bcb + (size_t)l0*32);
        for (int t = i; t < 64*32/4; t += 16)
            reinterpret_cast<float4*>(sBC)[t] = src[t];
        __syncwarp(mask);
        for (int ll = 0; ll < 64; ll++) {
            int l = l0 + ll;
            float Bv = sBC[ll*32 + i];
            float Cv = sBC[ll*32 + 16 + i];
            const float* Ar = &sAt[((l & 15) << 8) + (i << 4)];
            float a0 = Cv, a1 = 0.f, a2 = 0.f, a3 = Bv * h;
            #pragma unroll
            for (int j = 0; j < 16; j += 4) {
                a0 = fmaf(Ar[j+0], __shfl_sync(mask, h, j+0), a0);
                a1 = fmaf(Ar[j+1], __shfl_sync(mask, h, j+1), a1);
                a2 = fmaf(Ar[j+2], __shfl_sync(mask, h, j+2), a2);
                a3 = fmaf(Ar[j+3], __shfl_sync(mask, h, j+3), a3);
            }
            h = tanh_fast((a0 + a1) + (a2 + a3));
            hsb[(size_t)l*DST + i] = h;
        }
    }
}

// ---------------- rank-16 update: out += hs @ Wred^T (fp32) ------------------
__global__ void rank16_add(float* __restrict__ out,
                           const float* __restrict__ hs,
                           const float* __restrict__ Wred) {
    int m = blockIdx.x;
    int t = threadIdx.x;
    __shared__ float sh[16];
    if (t < 16) sh[t] = hs[(size_t)m * 16 + t];
    __syncthreads();
    float4 v = reinterpret_cast<float4*>(out)[(size_t)m * 256 + t];
    int n0 = t * 4;
    #pragma unroll
    for (int s = 0; s < 16; s++) {
        float hv = sh[s];
        v.x = fmaf(hv, Wred[(n0+0)*16 + s], v.x);
        v.y = fmaf(hv, Wred[(n0+1)*16 + s], v.y);
        v.z = fmaf(hv, Wred[(n0+2)*16 + s], v.z);
        v.w = fmaf(hv, Wred[(n0+3)*16 + s], v.w);
    }
    reinterpret_cast<float4*>(out)[(size_t)m * 256 + t] = v;
}

// ---------------- stream / event singletons ----------------------------------
static cudaStream_t side_stream() {
    static cudaStream_t s = []() {
        cudaStream_t t;
        cudaStreamCreateWithFlags(&t, cudaStreamNonBlocking);
        return t;
    }();
    return s;
}
static cudaEvent_t ev(int i) {
    static cudaEvent_t e[5] = {nullptr, nullptr, nullptr, nullptr, nullptr};
    if (!e[0])
        for (int k = 0; k < 5; k++)
            cudaEventCreateWithFlags(&e[k], cudaEventDisableTiming);
    return e[i];
}

// ---------------- launcher ----------------------------------------------------
extern "C" void kernel_launch(void* const* d_in, const int* in_sizes, int n_in,
                              void* d_out, int out_size)
{
    const float* x      = (const float*)d_in[0];
    const float* W_in   = (const float*)d_in[1];
    const float* b_in   = (const float*)d_in[2];
    const float* conv_w = (const float*)d_in[3];
    const float* conv_b = (const float*)d_in[4];
    const float* W_x    = (const float*)d_in[5];
    const float* b_x    = (const float*)d_in[6];
    const float* dt     = (const float*)d_in[7];
    const float* A      = (const float*)d_in[8];
    const float* W_out  = (const float*)d_in[10];
    const float* b_out  = (const float*)d_in[11];
    float* out = (float*)d_out;

    float *bcv, *hsp, *Atp, *Wred, *bconst, *zerov;
    __half *xib, *xsb, *xh, *xl, *winh, *winTh, *woh, *wol, *wcombh, *wxh;
    cudaGetSymbolAddress((void**)&xib,    g_xib);
    cudaGetSymbolAddress((void**)&xsb,    g_xsb);
    cudaGetSymbolAddress((void**)&bcv,    g_bc);
    cudaGetSymbolAddress((void**)&hsp,    g_hs);
    cudaGetSymbolAddress((void**)&Atp,    g_At);
    cudaGetSymbolAddress((void**)&Wred,   g_Wred);
    cudaGetSymbolAddress((void**)&bconst, g_bconst);
    cudaGetSymbolAddress((void**)&zerov,  g_zero);
    cudaGetSymbolAddress((void**)&xh,     g_xh);
    cudaGetSymbolAddress((void**)&xl,     g_xl);
    cudaGetSymbolAddress((void**)&winh,   g_winh);
    cudaGetSymbolAddress((void**)&winTh,  g_winTh);
    cudaGetSymbolAddress((void**)&woh,    g_woh);
    cudaGetSymbolAddress((void**)&wol,    g_wol);
    cudaGetSymbolAddress((void**)&wcombh, g_wcombh);
    cudaGetSymbolAddress((void**)&wxh,    g_wxh);

    // smem sizes
    const int SM_BIG1 = 3 * (16384 + 32768) + 1024;            // big P1: 145K
    const int SM_BIG2 = 3 * (2*16384 + 32768) + 1024;          // big P2: 193K
    const int SM_BC   = 3 * (16384 + 64*128) + 1024;           // small P1 BN64
    const int SM_WC   = 3 * (2*16384 + 64*128) + 1024;         // small P2 BN64
    cudaFuncSetAttribute(gemm_big<2,1>, cudaFuncAttributeMaxDynamicSharedMemorySize, SM_BIG1);
    cudaFuncSetAttribute(gemm_big<1,2>, cudaFuncAttributeMaxDynamicSharedMemorySize, SM_BIG2);
    cudaFuncSetAttribute(gemm_mma<4,1,64>, cudaFuncAttributeMaxDynamicSharedMemorySize, SM_BC);
    cudaFuncSetAttribute(gemm_mma<2,2,64>, cudaFuncAttributeMaxDynamicSharedMemorySize, SM_WC);

    cudaStream_t sd = side_stream();
    cudaEvent_t e_fork = ev(0), e_x = ev(1), e_hs = ev(2), e_done = ev(3), e_bc = ev(4);

    // ---- fork side stream at capture start ----
    cudaEventRecord(e_fork, 0);
    cudaStreamWaitEvent(sd, e_fork, 0);

    // ==== stream 0: xi chain (gemm1a kept at kernel-launch #4 for profiling) ====
    split_f32_v4<<<(int)(((long)MROWS*DMOD/4 + 255)/256), 256>>>(x, xh, xl, (long)MROWS*DMOD/4);
    cudaEventRecord(e_x, 0);
    split_hi_v4<<<(int)(((long)DINN*DMOD/4 + 255)/256), 256>>>(W_in, winh, (long)DINN*DMOD/4);
    prep_at<<<16, 256>>>(dt, A, Atp);
    gemm_big<2,1><<<dim3(DINN/256, MROWS/128), 256, SM_BIG1>>>(        // kernel #4
        xh, nullptr, DMOD, winh, DMOD, b_in,
        nullptr, 0, xib, DINN, DMOD);
    cudaMemsetAsync(bcv, 0, (size_t)MROWS * 32 * sizeof(float), 0);
    conv_silu<<<(MROWS*DINN)/256, 256>>>(xib, conv_w, conv_b, xsb);
    prep_wx<<<(128*DINN + 255)/256, 256>>>(W_x, wxh);
    // split-K GEMM3: 4 slices of K=512, atomicAdd into zeroed bc
    gemm_mma<4,1,64><<<dim3(4, MROWS/128), 256, SM_BC>>>(
        xsb, nullptr, DINN, wxh, DINN, b_x,
        bcv, 32, nullptr, 0, 512);
    cudaEventRecord(e_bc, 0);
    scan_kernel<<<BATCH, 16>>>(bcv, Atp, hsp);
    cudaEventRecord(e_hs, 0);

    // ==== side stream: weight preps + Wcomb (cheap; overlaps xi chain) ====
    split_f32_v4<<<(int)(((long)DMOD*DINN/4 + 255)/256), 256, 0, sd>>>(
        W_out, woh, wol, (long)DMOD*DINN/4);
    transpose_hi<<<dim3(DINN/32, DMOD/32), dim3(32, 8), 0, sd>>>(
        W_in + (size_t)DINN*DMOD, winTh);
    prep_wred<<<64, 256, 0, sd>>>(W_out, Wred);
    prep_bconst<<<DMOD/8, 256, 0, sd>>>(W_out, b_in + DINN, b_out, bconst);
    gemm_mma<2,2,64><<<dim3(DMOD/64, DMOD/128), 256, SM_WC, sd>>>(
        woh, wol, DINN, winTh, DINN, zerov,
        nullptr, 0, wcombh, DMOD, DINN);

    // GEMM2 deliberately scheduled into the scan window: wait for bc (i.e. the
    // end of stream-0's SM-saturating chain) so it runs concurrently with the
    // 4-CTA scan instead of contending with GEMM1a/conv/GEMM3.
    cudaStreamWaitEvent(sd, e_x, 0);
    cudaStreamWaitEvent(sd, e_bc, 0);
    gemm_big<1,2><<<dim3(DMOD/256, MROWS/128), 256, SM_BIG2, sd>>>(
        xh, xl, DMOD, wcombh, DMOD, bconst,
        out, DMOD, nullptr, 0, DMOD);
    cudaStreamWaitEvent(sd, e_hs, 0);
    rank16_add<<<MROWS, 256, 0, sd>>>(out, hsp, Wred);
    cudaEventRecord(e_done, sd);

    // ---- join side stream before capture ends ----
    cudaStreamWaitEvent(0, e_done, 0);
}

// round 13
// speedup vs baseline: 1.3706x; 1.0201x over previous
#include <cuda_runtime.h>
#include <cuda_fp16.h>
#include <math.h>
#include <stdint.h>

#define BATCH 4
#define LSEQ  2048
#define DMOD  1024
#define DST   16
#define KCONV 4
#define DINN  2048
#define MROWS (BATCH*LSEQ)   /* 8192 */

// ---------------- scratch (device globals) -----------------------------------
__device__ __align__(128) __half g_xib[(size_t)MROWS * DINN];
__device__ __align__(128) __half g_xsb[(size_t)MROWS * DINN];
__device__ __align__(128) float g_bc[(size_t)MROWS * 32];
__device__ __align__(128) float g_hs[(size_t)MROWS * DST];
__device__ __align__(128) float g_At[16*16*16];
__device__ __align__(128) float g_Wred[DMOD*DST];
__device__ __align__(128) float g_bconst[DMOD];
__device__ __align__(128) float g_zero[DMOD];
__device__ __align__(128) __half g_xh[(size_t)MROWS*DMOD];
__device__ __align__(128) __half g_winh[(size_t)DINN*DMOD];
__device__ __align__(128) __half g_winTh[(size_t)DMOD*DINN];
__device__ __align__(128) __half g_woh[(size_t)DMOD*DINN], g_wol[(size_t)DMOD*DINN];
__device__ __align__(128) __half g_wcombh[(size_t)DMOD*DMOD];
__device__ __align__(128) __half g_wxh[(size_t)128*DINN];

// ============================ PTX helpers (arch-agnostic) ====================
__device__ __forceinline__ uint32_t smem_u32(const void* p) {
    uint32_t a;
    asm("{ .reg .u64 t; cvta.to.shared.u64 t, %1; cvt.u32.u64 %0, t; }"
        : "=r"(a) : "l"(p));
    return a;
}
__device__ __forceinline__ void cp16(uint32_t s, const void* g) {
    asm volatile("cp.async.cg.shared.global [%0], [%1], 16;" :: "r"(s), "l"(g));
}
#define CP_COMMIT() asm volatile("cp.async.commit_group;" ::: "memory")
template<int N> __device__ __forceinline__ void cp_wait() {
    asm volatile("cp.async.wait_group %0;" :: "n"(N) : "memory");
}
__device__ __forceinline__ void ldsm_x4(uint32_t& r0, uint32_t& r1,
                                        uint32_t& r2, uint32_t& r3, uint32_t a) {
    asm volatile("ldmatrix.sync.aligned.m8n8.x4.shared.b16 {%0,%1,%2,%3}, [%4];"
                 : "=r"(r0), "=r"(r1), "=r"(r2), "=r"(r3) : "r"(a));
}
__device__ __forceinline__ void mma16816(float* c,
    uint32_t a0, uint32_t a1, uint32_t a2, uint32_t a3, uint32_t b0, uint32_t b1) {
    asm volatile(
        "mma.sync.aligned.m16n8k16.row.col.f32.f16.f16.f32 "
        "{%0,%1,%2,%3}, {%4,%5,%6,%7}, {%8,%9}, {%0,%1,%2,%3};"
        : "+f"(c[0]), "+f"(c[1]), "+f"(c[2]), "+f"(c[3])
        : "r"(a0), "r"(a1), "r"(a2), "r"(a3), "r"(b0), "r"(b1));
}
__device__ __forceinline__ float tanh_fast(float x) {
    float r;
    asm("tanh.approx.f32 %0, %1;" : "=f"(r) : "f"(x));
    return r;
}
__device__ __forceinline__ uint32_t swz(uint32_t bo) { return bo ^ ((bo >> 3) & 0x70); }

// 256-thread tile loader (ROWS x 64 fp16 = ROWS x 128B, SW128 swizzled)
template<int ROWS>
__device__ __forceinline__ void load_tile_async(const __half* __restrict__ g,
                                                long row0, int ld, int k0,
                                                uint32_t sb, int tid) {
    #pragma unroll
    for (int t = 0; t < ROWS/32; t++) {
        int idx = tid + t * 256;
        int r = idx >> 3, cv = idx & 7;
        cp16(sb + swz((uint32_t)(r * 128 + cv * 16)),
             g + (row0 + r) * (long)ld + k0 + cv * 8);
    }
}

// ============== BIG-TILE GEMM: CTA 128x256, 8 warps 2x4, warp 64x64 ==========
// MODE 1: fp32 + bias out    MODE 2: fp16 + bias out
// PASSES 1: Ah*Bh            PASSES 2: Ah*Bh + Al*Bh (A split, B hi-only)
template<int MODE, int PASSES>
__global__ __launch_bounds__(256, 1)
void gemm_big(const __half* __restrict__ Ah, const __half* __restrict__ Al, int lda,
              const __half* __restrict__ Bh, int ldb,
              const float* __restrict__ bias,
              float* __restrict__ Cout, int ldc,
              __half* __restrict__ outh, int ldr,
              int K)
{
    constexpr int ATILE = 16384;             // 128 x 128B
    constexpr int BTILE = 32768;             // 256 x 128B
    constexpr int OFF_AL = ATILE;
    constexpr int OFF_BH = (PASSES == 2) ? 2*ATILE : ATILE;
    constexpr int STAGE  = OFF_BH + BTILE;

    extern __shared__ char smem_raw[];
    uint32_t raw = smem_u32(smem_raw);
    const uint32_t sbase = (raw + 1023u) & ~1023u;

    const int tid  = threadIdx.x;
    const int wid  = tid >> 5, lane = tid & 31;
    const int warpM = wid & 1, warpN = wid >> 1;       // 2 x 4
    const long m0 = (long)blockIdx.y * 128;
    const int  n0 = blockIdx.x * 256;

    float acc[4][8][4];
    #pragma unroll
    for (int i = 0; i < 4; i++)
        #pragma unroll
        for (int j = 0; j < 8; j++)
            #pragma unroll
            for (int q = 0; q < 4; q++) acc[i][j][q] = 0.f;

    const int rowA0 = warpM * 64 + (lane & 7) + ((lane >> 3) & 1) * 8;
    const int khA   = (lane >> 4) & 1;
    const int rowB0 = warpN * 64 + (lane & 7) + ((lane >> 4) & 1) * 8;
    const int khB   = (lane >> 3) & 1;

    const int NC = K / 64;

    auto issue = [&](int c) {
        uint32_t st = sbase + (uint32_t)(c % 3) * STAGE;
        int k0 = c * 64;
        load_tile_async<128>(Ah, m0, lda, k0, st, tid);
        if (PASSES == 2) load_tile_async<128>(Al, m0, lda, k0, st + OFF_AL, tid);
        load_tile_async<256>(Bh, n0, ldb, k0, st + OFF_BH, tid);
        CP_COMMIT();
    };

    issue(0);
    if (NC > 1) issue(1);

    for (int c = 0; c < NC; c++) {
        if (c + 1 < NC) cp_wait<1>();
        else            cp_wait<0>();
        __syncthreads();
        if (c + 2 < NC) issue(c + 2);

        uint32_t st = sbase + (uint32_t)(c % 3) * STAGE;
        #pragma unroll
        for (int ks = 0; ks < 4; ks++) {
            uint32_t ah[4][4], al[4][4], bh[8][2];
            #pragma unroll
            for (int mi = 0; mi < 4; mi++) {
                uint32_t bo = swz((uint32_t)((rowA0 + mi*16) * 128 + ks*32 + khA*16));
                ldsm_x4(ah[mi][0], ah[mi][1], ah[mi][2], ah[mi][3], st + bo);
                if (PASSES == 2)
                    ldsm_x4(al[mi][0], al[mi][1], al[mi][2], al[mi][3], st + OFF_AL + bo);
            }
            #pragma unroll
            for (int nb = 0; nb < 4; nb++) {
                uint32_t bo = swz((uint32_t)((rowB0 + nb*16) * 128 + ks*32 + khB*16));
                ldsm_x4(bh[nb*2][0], bh[nb*2][1], bh[nb*2+1][0], bh[nb*2+1][1],
                        st + OFF_BH + bo);
            }
            #pragma unroll
            for (int mi = 0; mi < 4; mi++)
                #pragma unroll
                for (int nf = 0; nf < 8; nf++)
                    mma16816(acc[mi][nf], ah[mi][0], ah[mi][1], ah[mi][2], ah[mi][3],
                             bh[nf][0], bh[nf][1]);
            if (PASSES == 2) {
                #pragma unroll
                for (int mi = 0; mi < 4; mi++)
                    #pragma unroll
                    for (int nf = 0; nf < 8; nf++)
                        mma16816(acc[mi][nf], al[mi][0], al[mi][1], al[mi][2], al[mi][3],
                                 bh[nf][0], bh[nf][1]);
            }
        }
    }

    const int g  = lane >> 2, tg = lane & 3;
    #pragma unroll
    for (int mi = 0; mi < 4; mi++) {
        #pragma unroll
        for (int h = 0; h < 2; h++) {
            long m = m0 + warpM * 64 + mi * 16 + h * 8 + g;
            #pragma unroll
            for (int nf = 0; nf < 8; nf++) {
                int n = n0 + warpN * 64 + nf * 8 + tg * 2;
                float2 bv = *reinterpret_cast<const float2*>(&bias[n]);
                float v0 = acc[mi][nf][h*2+0] + bv.x;
                float v1 = acc[mi][nf][h*2+1] + bv.y;
                if (MODE == 2) {
                    __half2 p;
                    p.x = __float2half_rn(v0);
                    p.y = __float2half_rn(v1);
                    *reinterpret_cast<__half2*>(&outh[m * (long)ldr + n]) = p;
                } else {
                    *reinterpret_cast<float2*>(&Cout[m * (long)ldc + n]) =
                        make_float2(v0, v1);
                }
            }
        }
    }
}

// ============== small GEMM: CTA 128xBN, 8 warps 4x2 ==========================
// MODE 2: fp16-hi out + bias
// MODE 4: split-K: blockIdx.x = K-slice, atomicAdd fp32, bias on slice 0, n<32
// PASSES 1: Ah*Bh   PASSES 2: Ah*Bh + Al*Bh
template<int MODE, int PASSES, int BN_>
__global__ __launch_bounds__(256, 1)
void gemm_mma(const __half* __restrict__ Ah, const __half* __restrict__ Al, int lda,
              const __half* __restrict__ Bh, int ldb,
              const float* __restrict__ bias,
              float* __restrict__ Cout, int ldc,
              __half* __restrict__ outh, int ldr,
              int K)
{
    constexpr int ATILE = 16384;
    constexpr int BTILE = BN_ * 128;
    constexpr int OFF_AL = ATILE;
    constexpr int OFF_BH = (PASSES == 2) ? 2*ATILE : ATILE;
    constexpr int STAGE  = OFF_BH + BTILE;
    constexpr int NF = BN_ / 16;
    constexpr int NB = BN_ / 32;

    extern __shared__ char smem_raw[];
    uint32_t raw = smem_u32(smem_raw);
    const uint32_t sbase = (raw + 1023u) & ~1023u;

    const int tid  = threadIdx.x;
    const int wid  = tid >> 5, lane = tid & 31;
    const int warpM = wid & 3, warpN = wid >> 2;
    const long m0 = (long)blockIdx.y * 128;
    const int  n0 = (MODE == 4) ? 0 : blockIdx.x * BN_;
    const int  koff = (MODE == 4) ? blockIdx.x * K : 0;

    float acc[2][NF][4];
    #pragma unroll
    for (int i = 0; i < 2; i++)
        #pragma unroll
        for (int j = 0; j < NF; j++)
            #pragma unroll
            for (int q = 0; q < 4; q++) acc[i][j][q] = 0.f;

    const int rowA0 = warpM * 32 + (lane & 7) + ((lane >> 3) & 1) * 8;
    const int khA   = (lane >> 4) & 1;
    const int rowB0 = warpN * (BN_/2) + (lane & 7) + ((lane >> 4) & 1) * 8;
    const int khB   = (lane >> 3) & 1;

    const int NC = K / 64;

    auto issue = [&](int c) {
        uint32_t st = sbase + (uint32_t)(c % 3) * STAGE;
        int k0 = c * 64 + koff;
        load_tile_async<128>(Ah, m0, lda, k0, st, tid);
        if (PASSES == 2) load_tile_async<128>(Al, m0, lda, k0, st + OFF_AL, tid);
        load_tile_async<BN_>(Bh, n0, ldb, k0, st + OFF_BH, tid);
        CP_COMMIT();
    };

    issue(0);
    if (NC > 1) issue(1);

    for (int c = 0; c < NC; c++) {
        if (c + 1 < NC) cp_wait<1>();
        else            cp_wait<0>();
        __syncthreads();
        if (c + 2 < NC) issue(c + 2);

        uint32_t st = sbase + (uint32_t)(c % 3) * STAGE;
        #pragma unroll
        for (int ks = 0; ks < 4; ks++) {
            uint32_t ah[2][4], al[2][4], bh[NF][2];
            #pragma unroll
            for (int mi = 0; mi < 2; mi++) {
                uint32_t bo = swz((uint32_t)((rowA0 + mi*16) * 128 + ks*32 + khA*16));
                ldsm_x4(ah[mi][0], ah[mi][1], ah[mi][2], ah[mi][3], st + bo);
                if (PASSES == 2)
                    ldsm_x4(al[mi][0], al[mi][1], al[mi][2], al[mi][3], st + OFF_AL + bo);
            }
            #pragma unroll
            for (int nb = 0; nb < NB; nb++) {
                uint32_t bo = swz((uint32_t)((rowB0 + nb*16) * 128 + ks*32 + khB*16));
                ldsm_x4(bh[nb*2][0], bh[nb*2][1], bh[nb*2+1][0], bh[nb*2+1][1],
                        st + OFF_BH + bo);
            }
            #pragma unroll
            for (int mi = 0; mi < 2; mi++)
                #pragma unroll
                for (int nf = 0; nf < NF; nf++)
                    mma16816(acc[mi][nf], ah[mi][0], ah[mi][1], ah[mi][2], ah[mi][3],
                             bh[nf][0], bh[nf][1]);
            if (PASSES == 2) {
                #pragma unroll
                for (int mi = 0; mi < 2; mi++)
                    #pragma unroll
                    for (int nf = 0; nf < NF; nf++)
                        mma16816(acc[mi][nf], al[mi][0], al[mi][1], al[mi][2], al[mi][3],
                                 bh[nf][0], bh[nf][1]);
            }
        }
    }

    const int g  = lane >> 2, tg = lane & 3;
    #pragma unroll
    for (int mi = 0; mi < 2; mi++) {
        #pragma unroll
        for (int h = 0; h < 2; h++) {
            long m = m0 + warpM * 32 + mi * 16 + h * 8 + g;
            #pragma unroll
            for (int nf = 0; nf < NF; nf++) {
                int n = n0 + warpN * (BN_/2) + nf * 8 + tg * 2;
                if (MODE == 4 && n >= 32) continue;
                float b0 = 0.f, b1 = 0.f;
                if (MODE != 4 || blockIdx.x == 0) {
                    float2 bv = *reinterpret_cast<const float2*>(&bias[n]);
                    b0 = bv.x; b1 = bv.y;
                }
                float v0 = acc[mi][nf][h*2+0] + b0;
                float v1 = acc[mi][nf][h*2+1] + b1;
                if (MODE == 4) {
                    atomicAdd(&Cout[m * (long)ldc + n],     v0);
                    atomicAdd(&Cout[m * (long)ldc + n + 1], v1);
                } else {
                    __half2 p;
                    p.x = __float2half_rn(v0);
                    p.y = __float2half_rn(v1);
                    *reinterpret_cast<__half2*>(&outh[m * (long)ldr + n]) = p;
                }
            }
        }
    }
}

// ---------------- prep kernels -----------------------------------------------
__global__ void prep_at(const float* __restrict__ dt, const float* __restrict__ A,
                        float* __restrict__ At) {
    int t = blockIdx.x * blockDim.x + threadIdx.x;
    if (t < 4096) {
        int j = t >> 8, e = t & 255;
        At[t] = expf(expf(dt[j]) * A[e]);
    }
}

__global__ void prep_wred(const float* __restrict__ Wout, float* __restrict__ Wred) {
    int t = blockIdx.x * blockDim.x + threadIdx.x;
    if (t < DMOD * DST) {
        int m = t >> 4, s = t & 15;
        float sum = 0.f;
        #pragma unroll 8
        for (int r = 0; r < DINN / DST; r++)
            sum += Wout[(size_t)m * DINN + r * DST + s];
        Wred[t] = sum;
    }
}

__global__ void split_f32_v4(const float* __restrict__ src,
                             __half* __restrict__ hi,
                             __half* __restrict__ lo, long n4) {
    long t = (long)blockIdx.x * blockDim.x + threadIdx.x;
    if (t < n4) {
        float4 v = reinterpret_cast<const float4*>(src)[t];
        __half h0 = __float2half_rn(v.x), h1 = __float2half_rn(v.y);
        __half h2 = __float2half_rn(v.z), h3 = __float2half_rn(v.w);
        __half2 ha; ha.x = h0; ha.y = h1;
        __half2 hb; hb.x = h2; hb.y = h3;
        __half2 la, lb;
        la.x = __float2half_rn(v.x - __half2float(h0));
        la.y = __float2half_rn(v.y - __half2float(h1));
        lb.x = __float2half_rn(v.z - __half2float(h2));
        lb.y = __float2half_rn(v.w - __half2float(h3));
        reinterpret_cast<__half2*>(hi)[t*2]   = ha;
        reinterpret_cast<__half2*>(hi)[t*2+1] = hb;
        reinterpret_cast<__half2*>(lo)[t*2]   = la;
        reinterpret_cast<__half2*>(lo)[t*2+1] = lb;
    }
}

__global__ void split_hi_v4(const float* __restrict__ src,
                            __half* __restrict__ hi, long n4) {
    long t = (long)blockIdx.x * blockDim.x + threadIdx.x;
    if (t < n4) {
        float4 v = reinterpret_cast<const float4*>(src)[t];
        __half2 ha; ha.x = __float2half_rn(v.x); ha.y = __float2half_rn(v.y);
        __half2 hb; hb.x = __float2half_rn(v.z); hb.y = __float2half_rn(v.w);
        reinterpret_cast<__half2*>(hi)[t*2]   = ha;
        reinterpret_cast<__half2*>(hi)[t*2+1] = hb;
    }
}

// transpose (hi only): src [DINN, DMOD] -> th [DMOD, DINN]
__global__ void transpose_hi(const float* __restrict__ src,
                             __half* __restrict__ th) {
    __shared__ float tile[32][33];
    int di0 = blockIdx.x * 32, dm0 = blockIdx.y * 32;
    int tx = threadIdx.x, ty = threadIdx.y;
    #pragma unroll
    for (int i = 0; i < 32; i += 8)
        tile[ty + i][tx] = src[(size_t)(di0 + ty + i) * DMOD + dm0 + tx];
    __syncthreads();
    #pragma unroll
    for (int i = 0; i < 32; i += 8) {
        size_t o = (size_t)(dm0 + ty + i) * DINN + di0 + tx;
        th[o] = __float2half_rn(tile[tx][ty + i]);
    }
}

__global__ void prep_bconst(const float* __restrict__ Wout,
                            const float* __restrict__ b2,
                            const float* __restrict__ bout,
                            float* __restrict__ bc) {
    int n = blockIdx.x * 8 + (threadIdx.x >> 5);
    int lane = threadIdx.x & 31;
    float s = 0.f;
    for (int k = lane; k < DINN; k += 32)
        s = fmaf(Wout[(size_t)n * DINN + k], b2[k], s);
    #pragma unroll
    for (int o = 16; o; o >>= 1) s += __shfl_xor_sync(0xffffffffu, s, o);
    if (lane == 0) bc[n] = s + bout[n];
}

__global__ void prep_wx(const float* __restrict__ Wx, __half* __restrict__ o) {
    int t = blockIdx.x * blockDim.x + threadIdx.x;
    if (t < 128 * DINN) {
        int n = t / DINN, k = t % DINN;
        o[t] = __float2half_rn((n < 32) ? Wx[(size_t)n * DINN + k] : 0.f);
    }
}

// ---------------- depthwise causal conv (K=4) + SiLU, half2 ------------------
__global__ void conv_silu(const __half* __restrict__ xi,
                          const float* __restrict__ w,
                          const float* __restrict__ cb,
                          __half* __restrict__ xs)
{
    long t = (long)blockIdx.x * blockDim.x + threadIdx.x;   // over MROWS*DINN/2
    if (t >= (long)MROWS * (DINN/2)) return;
    int  c2 = (int)(t & (DINN/2 - 1)) * 2;
    long bl = t >> 10;
    int  l  = (int)(bl & (LSEQ - 1));
    long row0 = bl - l;

    float4 w0 = *reinterpret_cast<const float4*>(&w[c2 * 4]);
    float4 w1 = *reinterpret_cast<const float4*>(&w[(c2 + 1) * 4]);
    float2 b  = *reinterpret_cast<const float2*>(&cb[c2]);
    float a0 = b.x, a1 = b.y;
    const float wk0[4] = {w0.x, w0.y, w0.z, w0.w};
    const float wk1[4] = {w1.x, w1.y, w1.z, w1.w};
    #pragma unroll
    for (int k = 0; k < KCONV; k++) {
        int ll = l - (KCONV - 1) + k;
        if (ll >= 0) {
            __half2 xv = *reinterpret_cast<const __half2*>(
                &xi[(size_t)(row0 + ll) * DINN + c2]);
            float2 xf = __half22float2(xv);
            a0 = fmaf(xf.x, wk0[k], a0);
            a1 = fmaf(xf.y, wk1[k], a1);
        }
    }
    a0 = a0 / (1.f + __expf(-a0));
    a1 = a1 / (1.f + __expf(-a1));
    __half2 o; o.x = __float2half_rn(a0); o.y = __float2half_rn(a1);
    *reinterpret_cast<__half2*>(&xs[(size_t)bl * DINN + c2]) = o;
}

// ---------------- sequential nonlinear scan ----------------------------------
__global__ void scan_kernel(const float* __restrict__ bc,
                            const float* __restrict__ At,
                            float* __restrict__ hs)
{
    const int b = blockIdx.x;
    const int i = threadIdx.x;
    const unsigned mask = 0xffffu;
    __shared__ float sAt[16*16*16];
    __shared__ float sBC[64*32];

    for (int t = i; t < 4096/4; t += 16)
        reinterpret_cast<float4*>(sAt)[t] = reinterpret_cast<const float4*>(At)[t];

    const float* bcb = bc + (size_t)b*LSEQ*32;
    float*       hsb = hs + (size_t)b*LSEQ*DST;
    float h = 0.f;

    for (int l0 = 0; l0 < LSEQ; l0 += 64) {
        __syncwarp(mask);
        const float4* src = reinterpret_cast<const float4*>(bcb + (size_t)l0*32);
        for (int t = i; t < 64*32/4; t += 16)
            reinterpret_cast<float4*>(sBC)[t] = src[t];
        __syncwarp(mask);
        for (int ll = 0; ll < 64; ll++) {
            int l = l0 + ll;
            float Bv = sBC[ll*32 + i];
            float Cv = sBC[ll*32 + 16 + i];
            const float* Ar = &sAt[((l & 15) << 8) + (i << 4)];
            float a0 = Cv, a1 = 0.f, a2 = 0.f, a3 = Bv * h;
            #pragma unroll
            for (int j = 0; j < 16; j += 4) {
                a0 = fmaf(Ar[j+0], __shfl_sync(mask, h, j+0), a0);
                a1 = fmaf(Ar[j+1], __shfl_sync(mask, h, j+1), a1);
                a2 = fmaf(Ar[j+2], __shfl_sync(mask, h, j+2), a2);
                a3 = fmaf(Ar[j+3], __shfl_sync(mask, h, j+3), a3);
            }
            h = tanh_fast((a0 + a1) + (a2 + a3));
            hsb[(size_t)l*DST + i] = h;
        }
    }
}

// ---------------- rank-16 update: out += hs @ Wred^T (fp32) ------------------
__global__ void rank16_add(float* __restrict__ out,
                           const float* __restrict__ hs,
                           const float* __restrict__ Wred) {
    int m = blockIdx.x;
    int t = threadIdx.x;
    __shared__ float sh[16];
    if (t < 16) sh[t] = hs[(size_t)m * 16 + t];
    __syncthreads();
    float4 v = reinterpret_cast<float4*>(out)[(size_t)m * 256 + t];
    int n0 = t * 4;
    #pragma unroll
    for (int s = 0; s < 16; s++) {
        float hv = sh[s];
        v.x = fmaf(hv, Wred[(n0+0)*16 + s], v.x);
        v.y = fmaf(hv, Wred[(n0+1)*16 + s], v.y);
        v.z = fmaf(hv, Wred[(n0+2)*16 + s], v.z);
        v.w = fmaf(hv, Wred[(n0+3)*16 + s], v.w);
    }
    reinterpret_cast<float4*>(out)[(size_t)m * 256 + t] = v;
}

// ---------------- stream / event singletons ----------------------------------
static cudaStream_t side_stream() {
    static cudaStream_t s = []() {
        cudaStream_t t;
        cudaStreamCreateWithFlags(&t, cudaStreamNonBlocking);
        return t;
    }();
    return s;
}
static cudaEvent_t ev(int i) {
    static cudaEvent_t e[5] = {nullptr, nullptr, nullptr, nullptr, nullptr};
    if (!e[0])
        for (int k = 0; k < 5; k++)
            cudaEventCreateWithFlags(&e[k], cudaEventDisableTiming);
    return e[i];
}

// ---------------- launcher ----------------------------------------------------
extern "C" void kernel_launch(void* const* d_in, const int* in_sizes, int n_in,
                              void* d_out, int out_size)
{
    const float* x      = (const float*)d_in[0];
    const float* W_in   = (const float*)d_in[1];
    const float* b_in   = (const float*)d_in[2];
    const float* conv_w = (const float*)d_in[3];
    const float* conv_b = (const float*)d_in[4];
    const float* W_x    = (const float*)d_in[5];
    const float* b_x    = (const float*)d_in[6];
    const float* dt     = (const float*)d_in[7];
    const float* A      = (const float*)d_in[8];
    const float* W_out  = (const float*)d_in[10];
    const float* b_out  = (const float*)d_in[11];
    float* out = (float*)d_out;

    float *bcv, *hsp, *Atp, *Wred, *bconst, *zerov;
    __half *xib, *xsb, *xh, *winh, *winTh, *woh, *wol, *wcombh, *wxh;
    cudaGetSymbolAddress((void**)&xib,    g_xib);
    cudaGetSymbolAddress((void**)&xsb,    g_xsb);
    cudaGetSymbolAddress((void**)&bcv,    g_bc);
    cudaGetSymbolAddress((void**)&hsp,    g_hs);
    cudaGetSymbolAddress((void**)&Atp,    g_At);
    cudaGetSymbolAddress((void**)&Wred,   g_Wred);
    cudaGetSymbolAddress((void**)&bconst, g_bconst);
    cudaGetSymbolAddress((void**)&zerov,  g_zero);
    cudaGetSymbolAddress((void**)&xh,     g_xh);
    cudaGetSymbolAddress((void**)&winh,   g_winh);
    cudaGetSymbolAddress((void**)&winTh,  g_winTh);
    cudaGetSymbolAddress((void**)&woh,    g_woh);
    cudaGetSymbolAddress((void**)&wol,    g_wol);
    cudaGetSymbolAddress((void**)&wcombh, g_wcombh);
    cudaGetSymbolAddress((void**)&wxh,    g_wxh);

    // smem sizes
    const int SM_BIG1 = 3 * (16384 + 32768) + 1024;            // big P1: 145K
    const int SM_BC   = 3 * (16384 + 64*128) + 1024;           // small P1 BN64
    const int SM_WC   = 3 * (2*16384 + 64*128) + 1024;         // small P2 BN64
    cudaFuncSetAttribute(gemm_big<2,1>, cudaFuncAttributeMaxDynamicSharedMemorySize, SM_BIG1);
    cudaFuncSetAttribute(gemm_big<1,1>, cudaFuncAttributeMaxDynamicSharedMemorySize, SM_BIG1);
    cudaFuncSetAttribute(gemm_mma<4,1,64>, cudaFuncAttributeMaxDynamicSharedMemorySize, SM_BC);
    cudaFuncSetAttribute(gemm_mma<2,2,64>, cudaFuncAttributeMaxDynamicSharedMemorySize, SM_WC);

    cudaStream_t sd = side_stream();
    cudaEvent_t e_fork = ev(0), e_x = ev(1), e_hs = ev(2), e_done = ev(3), e_bc = ev(4);

    // ---- fork side stream at capture start ----
    cudaEventRecord(e_fork, 0);
    cudaStreamWaitEvent(sd, e_fork, 0);

    // ==== stream 0: xi chain (gemm1a kept at kernel #4 for profiling) ====
    split_hi_v4<<<(int)(((long)MROWS*DMOD/4 + 255)/256), 256>>>(x, xh, (long)MROWS*DMOD/4);
    cudaEventRecord(e_x, 0);
    split_hi_v4<<<(int)(((long)DINN*DMOD/4 + 255)/256), 256>>>(W_in, winh, (long)DINN*DMOD/4);
    prep_at<<<16, 256>>>(dt, A, Atp);
    gemm_big<2,1><<<dim3(DINN/256, MROWS/128), 256, SM_BIG1>>>(        // kernel #4
        xh, nullptr, DMOD, winh, DMOD, b_in,
        nullptr, 0, xib, DINN, DMOD);
    cudaMemsetAsync(bcv, 0, (size_t)MROWS * 32 * sizeof(float), 0);
    conv_silu<<<(int)(((long)MROWS*(DINN/2) + 255)/256), 256>>>(xib, conv_w, conv_b, xsb);
    prep_wx<<<(128*DINN + 255)/256, 256>>>(W_x, wxh);
    // split-K GEMM3: 4 slices of K=512, atomicAdd into zeroed bc
    gemm_mma<4,1,64><<<dim3(4, MROWS/128), 256, SM_BC>>>(
        xsb, nullptr, DINN, wxh, DINN, b_x,
        bcv, 32, nullptr, 0, 512);
    cudaEventRecord(e_bc, 0);
    scan_kernel<<<BATCH, 16>>>(bcv, Atp, hsp);
    cudaEventRecord(e_hs, 0);

    // ==== side stream: weight preps + Wcomb (cheap; overlaps xi chain) ====
    split_f32_v4<<<(int)(((long)DMOD*DINN/4 + 255)/256), 256, 0, sd>>>(
        W_out, woh, wol, (long)DMOD*DINN/4);
    transpose_hi<<<dim3(DINN/32, DMOD/32), dim3(32, 8), 0, sd>>>(
        W_in + (size_t)DINN*DMOD, winTh);
    prep_wred<<<64, 256, 0, sd>>>(W_out, Wred);
    prep_bconst<<<DMOD/8, 256, 0, sd>>>(W_out, b_in + DINN, b_out, bconst);
    gemm_mma<2,2,64><<<dim3(DMOD/64, DMOD/128), 256, SM_WC, sd>>>(
        woh, wol, DINN, winTh, DINN, zerov,
        nullptr, 0, wcombh, DMOD, DINN);

    // GEMM2 scheduled into the scan window (1-pass now: x_h @ wcomb_h)
    cudaStreamWaitEvent(sd, e_x, 0);
    cudaStreamWaitEvent(sd, e_bc, 0);
    gemm_big<1,1><<<dim3(DMOD/256, MROWS/128), 256, SM_BIG1, sd>>>(
        xh, nullptr, DMOD, wcombh, DMOD, bconst,
        out, DMOD, nullptr, 0, DMOD);
    cudaStreamWaitEvent(sd, e_hs, 0);
    rank16_add<<<MROWS, 256, 0, sd>>>(out, hsp, Wred);
    cudaEventRecord(e_done, sd);

    // ---- join side stream before capture ends ----
    cudaStreamWaitEvent(0, e_done, 0);
}